// round 13
// baseline (speedup 1.0000x reference)
#include <cuda_runtime.h>
#include <cstdint>
#include <math.h>

#define SEQ 256
#define NB 64
#define HID 300
#define G4 1200
#define NTAG 12

// recurrence: 2 dirs x 8 batch-groups x 8 unit-slices = 128 CTAs  (R10 core, direct-L2 h)
#define RBG 8
#define RUS 8
#define RBS 8
#define RUPC 38
#define R_P 76
#define R_KS 8
#define R_ACT 608
#define R_THREADS 640

// input projection: persistent weights; 7 seq-splits x 20 m x 2 dirs = 280 CTAs (one wave)
// s-blocked: 3 sequence positions per pass share each weight LDS
#define IP_MB 20
#define IP_ROWS 60
#define IP_THREADS 320
#define IP_JS 7
#define IP_SC 37
#define IP_KC 20
#define IP_NKC 15
#define IP_CHF (IP_KC * NB)       // 1280 floats per chunk per stream
#define IP_CH4 (IP_CHF / 4)       // 320 float4 per chunk per stream

typedef unsigned long long ull;

__device__ __forceinline__ ull pack2(float lo, float hi) {
    ull r; asm("mov.b64 %0, {%1, %2};" : "=l"(r) : "f"(lo), "f"(hi)); return r;
}
__device__ __forceinline__ void unpack2(ull v, float& lo, float& hi) {
    asm("mov.b64 {%0, %1}, %2;" : "=f"(lo), "=f"(hi) : "l"(v));
}
__device__ __forceinline__ ull fma2(ull a, ull b, ull c) {
    ull d; asm("fma.rn.f32x2 %0, %1, %2, %3;" : "=l"(d) : "l"(a), "l"(b), "l"(c)); return d;
}
__device__ __forceinline__ ull add2(ull a, ull b) {
    ull d; asm("add.rn.f32x2 %0, %1, %2;" : "=l"(d) : "l"(a), "l"(b)); return d;
}
__device__ __forceinline__ float ftanh(float x) {
    float y; asm("tanh.approx.f32 %0, %1;" : "=f"(y) : "f"(x)); return y;
}
__device__ __forceinline__ float fsigm(float x) {
    return 0.5f * ftanh(0.5f * x) + 0.5f;
}
__device__ __forceinline__ uint32_t smem_u32_of(const void* p) {
    uint32_t a;
    asm("{ .reg .u64 t0; cvta.to.shared.u64 t0, %1; cvt.u32.u64 %0, t0; }" : "=r"(a) : "l"(p));
    return a;
}
__device__ __forceinline__ void cpasync16(uint32_t saddr, const void* g) {
    asm volatile("cp.async.cg.shared.global [%0], [%1], 16;" :: "r"(saddr), "l"(g));
}

// ---------------- scratch (device globals; no allocations) ----------------
__device__ float g_XT[SEQ * HID * NB];
__device__ float g_G[2][SEQ][G4 * NB];
__device__ float g_hall[2][SEQ][RBG * HID * RBS];
__device__ float g_emit[SEQ][NB][NTAG];
__device__ int   g_cnt2[16][32];

extern __shared__ float sm[];

// ---------------- embedding gather + transpose (+ counter reset) ----------------
__global__ void k_gather(const int* __restrict__ sent, const float* __restrict__ emb) {
    int s = blockIdx.x;
    __shared__ float sx[64][33];
    __shared__ int rows[64];
    int t = threadIdx.x;  // 256
    if (s == 0 && t < 16) g_cnt2[t][0] = 0;
    if (t < 64) rows[t] = sent[t * SEQ + s];
    __syncthreads();
    for (int kc = 0; kc < 10; kc++) {
        int kbase = kc * 32;
        int width = HID - kbase; if (width > 32) width = 32;
        int kk = t & 31, bg = t >> 5;
        if (kk < width) {
            for (int b = bg; b < 64; b += 8)
                sx[b][kk] = emb[rows[b] * HID + kbase + kk];
        }
        __syncthreads();
        int b = t & 63, kg = t >> 6;
        for (int k2 = kg; k2 < width; k2 += 4)
            g_XT[(s * HID + kbase + k2) * NB + b] = sx[b][k2];
        __syncthreads();
    }
}

// ---------------- input projection: persistent weights, s-blocked (3 s per pass) ----------------
__global__ void __launch_bounds__(IP_THREADS, 2) k_inproj(
    const float* __restrict__ Wf, const float* __restrict__ bf,
    const float* __restrict__ Wb, const float* __restrict__ bb)
{
    int j = blockIdx.x, m = blockIdx.y, d = blockIdx.z;
    const float* W    = d ? Wb : Wf;
    const float* bias = d ? bb : bf;
    float* ws = sm;                        // 18000 floats: ws[k*60 + r]
    float* xb = sm + HID * IP_ROWS;        // 6 x 1280 floats: [buf][stream]
    int t = threadIdx.x;
    int u0 = m * 15;

    int s0 = j * IP_SC;
    int ns = SEQ - s0; if (ns > IP_SC) ns = IP_SC;
    int ntrip = (ns + 2) / 3;
    int slast = s0 + ns - 1;

    uint32_t xb_u32 = smem_u32_of(xb);

    for (int idx = t; idx < HID * IP_ROWS; idx += IP_THREADS) {
        int k = idx / IP_ROWS, r = idx - k * IP_ROWS;
        int ul = r >> 2, gate = r & 3;
        ws[idx] = W[(gate * HID + u0 + ul) * HID + k];
    }

    int b = t & 63, rg = t >> 6;

    float bv[12];
    int rowv[12];
#pragma unroll
    for (int q = 0; q < 12; q++) {
        int r = rg * 12 + q;
        int row = (r & 3) * HID + u0 + (r >> 2);
        rowv[q] = row;
        bv[q] = bias[row];
    }
    __syncthreads();   // ws ready

    for (int tr = 0; tr < ntrip; tr++) {
        int sA = s0 + 3 * tr;
        int sB = sA + 1; if (sB > slast) sB = slast;
        int sC = sA + 2; if (sC > slast) sC = slast;
        const float4* gS[3];
        gS[0] = (const float4*)(g_XT + (long long)sA * (HID * NB));
        gS[1] = (const float4*)(g_XT + (long long)sB * (HID * NB));
        gS[2] = (const float4*)(g_XT + (long long)sC * (HID * NB));

#pragma unroll
        for (int q = 0; q < 3; q++) {
            uint32_t dst = xb_u32 + (q * IP_CHF + t * 4) * 4;
            cpasync16(dst, gS[q] + t);
        }
        asm volatile("cp.async.commit_group;");

        ull accA[6], accB[6], accC[6];
#pragma unroll
        for (int p = 0; p < 6; p++) { accA[p] = 0ull; accB[p] = 0ull; accC[p] = 0ull; }

        const ulonglong2* wp = ((const ulonglong2*)ws) + rg * 3;

        for (int kc = 0; kc < IP_NKC; kc++) {
            int cur = kc & 1;
            if (kc < IP_NKC - 1) {
                int nb4 = (kc + 1) * IP_CH4;
                uint32_t bufb = xb_u32 + ((kc + 1) & 1) * (3 * IP_CHF * 4);
#pragma unroll
                for (int q = 0; q < 3; q++) {
                    uint32_t dst = bufb + (q * IP_CHF + t * 4) * 4;
                    cpasync16(dst, gS[q] + nb4 + t);
                }
                asm volatile("cp.async.commit_group;");
                asm volatile("cp.async.wait_group 1;");
            } else {
                asm volatile("cp.async.wait_group 0;");
            }
            __syncthreads();

            const float* base = xb + cur * (3 * IP_CHF);
            const float* xpA = base + b;
            const float* xpB = base + IP_CHF + b;
            const float* xpC = base + 2 * IP_CHF + b;
#pragma unroll 5
            for (int k = 0; k < IP_KC; k++) {
                float xa = xpA[k * NB];
                float xv = xpB[k * NB];
                float xc = xpC[k * NB];
                ull h2a = pack2(xa, xa);
                ull h2b = pack2(xv, xv);
                ull h2c = pack2(xc, xc);
                ulonglong2 w0 = wp[0], w1 = wp[1], w2 = wp[2];
                accA[0] = fma2(w0.x, h2a, accA[0]); accB[0] = fma2(w0.x, h2b, accB[0]); accC[0] = fma2(w0.x, h2c, accC[0]);
                accA[1] = fma2(w0.y, h2a, accA[1]); accB[1] = fma2(w0.y, h2b, accB[1]); accC[1] = fma2(w0.y, h2c, accC[1]);
                accA[2] = fma2(w1.x, h2a, accA[2]); accB[2] = fma2(w1.x, h2b, accB[2]); accC[2] = fma2(w1.x, h2c, accC[2]);
                accA[3] = fma2(w1.y, h2a, accA[3]); accB[3] = fma2(w1.y, h2b, accB[3]); accC[3] = fma2(w1.y, h2c, accC[3]);
                accA[4] = fma2(w2.x, h2a, accA[4]); accB[4] = fma2(w2.x, h2b, accB[4]); accC[4] = fma2(w2.x, h2c, accC[4]);
                accA[5] = fma2(w2.y, h2a, accA[5]); accB[5] = fma2(w2.y, h2b, accB[5]); accC[5] = fma2(w2.y, h2c, accC[5]);
                wp += 15;
            }
            __syncthreads();
        }

        float* GdA = g_G[d][sA];
        float* GdB = g_G[d][sB];
        float* GdC = g_G[d][sC];
#pragma unroll
        for (int p = 0; p < 6; p++) {
            float a0, a1, b0, b1, c0x, c1x;
            unpack2(accA[p], a0, a1);
            unpack2(accB[p], b0, b1);
            unpack2(accC[p], c0x, c1x);
            int ra = rowv[2 * p], rb = rowv[2 * p + 1];
            GdA[ra * NB + b] = a0 + bv[2 * p];
            GdA[rb * NB + b] = a1 + bv[2 * p + 1];
            GdB[ra * NB + b] = b0 + bv[2 * p];
            GdB[rb * NB + b] = b1 + bv[2 * p + 1];
            GdC[ra * NB + b] = c0x + bv[2 * p];
            GdC[rb * NB + b] = c1x + bv[2 * p + 1];
        }
    }
}

// ---------------- persistent LSTM recurrence: 640 threads, 8-way k-split, direct-L2 h ----------------
// GEMV reads h straight from global (warp-uniform LDG broadcast, latency hidden by MLP);
// no smem staging, no S2 barrier. smem: ws 182400B + red 38912B = 221312B.
__global__ void __launch_bounds__(R_THREADS, 1) k_recur(
    const float* __restrict__ Whf, const float* __restrict__ Whb)
{
    int bid = blockIdx.x;
    int d = bid >> 6;
    int g = (bid >> 3) & 7;
    int m = bid & 7;
    const float* W = d ? Whb : Whf;

    float* ws = sm;                    // ws[k*152 + r], row pairs packed as ull
    ull*  red = (ull*)(sm + HID * 152);   // 8 * 608 ull

    int t = threadIdx.x;
    int u0 = m * RUPC;
    int cu = HID - u0; if (cu > RUPC) cu = RUPC;

    for (int idx = t; idx < HID * 152; idx += R_THREADS) {
        int k = idx / 152, r = idx - k * 152;
        int ul = r >> 2, gate = r & 3;
        ws[idx] = (ul < cu) ? W[(gate * HID + u0 + ul) * HID + k] : 0.f;
    }
    __syncthreads();

    int ks = t / R_P;                  // 0..7 active, 8 = spare warp
    int p  = t - ks * R_P;             // rowpair 0..75
    bool gemv = (t < R_ACT);
    int k0   = (ks < 4) ? 38 * ks : 152 + 37 * (ks - 4);
    int klen = (ks < 4) ? 38 : 37;
    if (!gemv) { k0 = 0; klen = 0; }
    int bp = (t < 304) ? ks : 0;
    int ul = p >> 1;
    bool doer = (t < 304) && ((p & 1) == 0) && (ul < cu);
    int boff = g * RBS + bp * 2;
    float c0 = 0.f, c1 = 0.f;
    int* cnt = &g_cnt2[d * 8 + g][0];
    const ull* wsu = (const ull*)ws;

    for (int step = 0; step < SEQ; step++) {
        int pos = d ? (SEQ - 1 - step) : step;
        const float* Gp = g_G[d][pos];

        float2 Gv0, Gv1, Gv2, Gv3;
        if (doer) {
            int gb = (u0 + ul) * NB + boff;
            Gv0 = *(const float2*)(Gp + 0 * HID * NB + gb);
            Gv1 = *(const float2*)(Gp + 1 * HID * NB + gb);
            Gv2 = *(const float2*)(Gp + 2 * HID * NB + gb);
            Gv3 = *(const float2*)(Gp + 3 * HID * NB + gb);
        }

        float s0lo = 0.f, s0hi = 0.f, s1lo = 0.f, s1hi = 0.f;

        if (step > 0) {
            if (t == 0) {
                int target = RUS * step;
                int v;
                do {
                    asm volatile("ld.acquire.gpu.global.b32 %0, [%1];" : "=r"(v) : "l"(cnt) : "memory");
                    if (v < target) __nanosleep(20);
                } while (v < target);
            }
            __syncthreads();   // S1: peers' h visible

            int prev = d ? (SEQ - step) : (step - 1);
            const ulonglong2* hg =
                (const ulonglong2*)(g_hall[d][prev] + g * (HID * RBS));

            // partial GEMV: 2 rows x 8 batches per thread; h read directly from L2
            ull a00 = 0, a01 = 0, a02 = 0, a03 = 0;
            ull a10 = 0, a11 = 0, a12 = 0, a13 = 0;
#pragma unroll 4
            for (int kk = 0; kk < klen; kk++) {
                int k = k0 + kk;
                ull w = wsu[k * R_P + p];
                float w0, w1; unpack2(w, w0, w1);
                ull w00 = pack2(w0, w0), w11 = pack2(w1, w1);
                ulonglong2 hA = __ldg(hg + k * 2);
                ulonglong2 hB = __ldg(hg + k * 2 + 1);
                a00 = fma2(w00, hA.x, a00); a01 = fma2(w00, hA.y, a01);
                a02 = fma2(w00, hB.x, a02); a03 = fma2(w00, hB.y, a03);
                a10 = fma2(w11, hA.x, a10); a11 = fma2(w11, hA.y, a11);
                a12 = fma2(w11, hB.x, a12); a13 = fma2(w11, hB.y, a13);
            }
            if (gemv) {
                red[0 * R_ACT + t] = a00; red[1 * R_ACT + t] = a01;
                red[2 * R_ACT + t] = a02; red[3 * R_ACT + t] = a03;
                red[4 * R_ACT + t] = a10; red[5 * R_ACT + t] = a11;
                red[6 * R_ACT + t] = a12; red[7 * R_ACT + t] = a13;
            }
            __syncthreads();   // S3: partials visible

            if (t < 304) {
                const ull* r0 = red + bp * R_ACT + p;
                const ull* r1 = red + (4 + bp) * R_ACT + p;
                ull s0 = r0[0];
                ull s1 = r1[0];
#pragma unroll
                for (int q = 1; q < R_KS; q++) {
                    s0 = add2(s0, r0[q * R_P]);
                    s1 = add2(s1, r1[q * R_P]);
                }
                unpack2(s0, s0lo, s0hi);
                unpack2(s1, s1lo, s1hi);
            }
        }

        float g2lo = __shfl_down_sync(0xffffffffu, s0lo, 1);
        float g2hi = __shfl_down_sync(0xffffffffu, s0hi, 1);
        float g3lo = __shfl_down_sync(0xffffffffu, s1lo, 1);
        float g3hi = __shfl_down_sync(0xffffffffu, s1hi, 1);

        if (doer) {
            float i0 = fsigm(s0lo + Gv0.x), i1 = fsigm(s0hi + Gv0.y);
            float f0 = fsigm(s1lo + Gv1.x), f1 = fsigm(s1hi + Gv1.y);
            float q0 = ftanh(g2lo + Gv2.x), q1 = ftanh(g2hi + Gv2.y);
            float o0 = fsigm(g3lo + Gv3.x), o1 = fsigm(g3hi + Gv3.y);
            c0 = f0 * c0 + i0 * q0;
            c1 = f1 * c1 + i1 * q1;
            float2 hv;
            hv.x = o0 * ftanh(c0);
            hv.y = o1 * ftanh(c1);
            *(float2*)(g_hall[d][pos] + g * (HID * RBS) + (u0 + ul) * RBS + bp * 2) = hv;
        }

        __syncthreads();   // S6: h stores done
        if (t == 0)
            asm volatile("red.release.gpu.global.add.s32 [%0], 1;" :: "l"(cnt) : "memory");
    }
}

// ---------------- emissions ----------------
__global__ void k_emit(const float* __restrict__ Wl, const float* __restrict__ bl) {
    int s = blockIdx.x, t = threadIdx.x;  // 256
    __shared__ float wl[600 * NTAG];
    __shared__ float red2[4 * NTAG * NB];
    for (int idx = t; idx < 600 * NTAG; idx += 256) {
        int k = idx / NTAG, j = idx - k * NTAG;
        wl[idx] = Wl[j * 600 + k];
    }
    __syncthreads();
    int b = t & 63, ksx = t >> 6;
    int gof = (b >> 3) * (HID * RBS) + (b & 7);
    float acc[NTAG];
#pragma unroll
    for (int j = 0; j < NTAG; j++) acc[j] = 0.f;
    const float* hf = g_hall[0][s];
    const float* hb = g_hall[1][s];
    int k0 = ksx * 150;
    for (int k = k0; k < k0 + 150; k++) {
        float v = (k < HID) ? hf[gof + k * RBS] : hb[gof + (k - HID) * RBS];
        const float4* w4 = (const float4*)(wl + k * NTAG);
#pragma unroll
        for (int q = 0; q < 3; q++) {
            float4 w = w4[q];
            acc[4 * q + 0] += w.x * v; acc[4 * q + 1] += w.y * v;
            acc[4 * q + 2] += w.z * v; acc[4 * q + 3] += w.w * v;
        }
    }
#pragma unroll
    for (int j = 0; j < NTAG; j++) red2[(ksx * NTAG + j) * NB + b] = acc[j];
    __syncthreads();
    for (int idx = t; idx < NTAG * NB; idx += 256) {
        int j = idx >> 6, b2 = idx & 63;
        float v = red2[(0 * NTAG + j) * NB + b2] + red2[(1 * NTAG + j) * NB + b2]
                + red2[(2 * NTAG + j) * NB + b2] + red2[(3 * NTAG + j) * NB + b2];
        g_emit[s][b2][j] = v + bl[j];
    }
}

// ---------------- CRF forward + gold score + loss ----------------
__global__ void k_crf(const int* __restrict__ tags, const float* __restrict__ trans,
                      float* __restrict__ out) {
    int b = blockIdx.x;
    int j = threadIdx.x;
    float Tcol[NTAG];
#pragma unroll
    for (int i = 0; i < NTAG; i++) Tcol[i] = (j < NTAG) ? trans[i * NTAG + j] : 0.f;
    float dcur = (j < NTAG) ? g_emit[0][b][j] : -1e30f;

    float ts = 0.f;
    for (int s = j; s < SEQ; s += 32) {
        int tg = tags[b * SEQ + s];
        ts += g_emit[s][b][tg];
        if (s < SEQ - 1) ts += trans[tg * NTAG + tags[b * SEQ + s + 1]];
    }
#pragma unroll
    for (int off = 16; off; off >>= 1) ts += __shfl_xor_sync(0xffffffffu, ts, off);

    for (int s = 1; s < SEQ; s++) {
        float v[NTAG];
#pragma unroll
        for (int i = 0; i < NTAG; i++)
            v[i] = __shfl_sync(0xffffffffu, dcur, i) + Tcol[i];
        float mx = v[0];
#pragma unroll
        for (int i = 1; i < NTAG; i++) mx = fmaxf(mx, v[i]);
        float sum = 0.f;
#pragma unroll
        for (int i = 0; i < NTAG; i++) sum += expf(v[i] - mx);
        float e = (j < NTAG) ? g_emit[s][b][j] : 0.f;
        dcur = e + mx + logf(sum);
    }

    float dd = (j < NTAG) ? dcur : -1e30f;
    float mm = dd;
#pragma unroll
    for (int off = 16; off; off >>= 1) mm = fmaxf(mm, __shfl_xor_sync(0xffffffffu, mm, off));
    float se = (j < NTAG) ? expf(dd - mm) : 0.f;
#pragma unroll
    for (int off = 16; off; off >>= 1) se += __shfl_xor_sync(0xffffffffu, se, off);
    if (j == 0) out[b] = mm + logf(se) - ts;
}

// ---------------- launch ----------------
extern "C" void kernel_launch(void* const* d_in, const int* in_sizes, int n_in,
                              void* d_out, int out_size) {
    const int*   sentences = (const int*)d_in[0];
    const int*   tags      = (const int*)d_in[1];
    const float* emb       = (const float*)d_in[2];
    const float* W_ih_f    = (const float*)d_in[3];
    const float* W_hh_f    = (const float*)d_in[4];
    const float* b_f       = (const float*)d_in[5];
    const float* W_ih_b    = (const float*)d_in[6];
    const float* W_hh_b    = (const float*)d_in[7];
    const float* b_b       = (const float*)d_in[8];
    const float* W_lin     = (const float*)d_in[9];
    const float* b_lin     = (const float*)d_in[10];
    const float* trans     = (const float*)d_in[11];
    float* out = (float*)d_out;

    int smem_ip = (HID * IP_ROWS + 6 * IP_CHF) * 4;       // 102720 B
    int smem_rc = HID * 152 * 4 + R_KS * R_ACT * 8;       // 221312 B
    cudaFuncSetAttribute(k_inproj, cudaFuncAttributeMaxDynamicSharedMemorySize, smem_ip);
    cudaFuncSetAttribute(k_recur,  cudaFuncAttributeMaxDynamicSharedMemorySize, smem_rc);

    k_gather<<<SEQ, 256>>>(sentences, emb);
    dim3 gip(IP_JS, IP_MB, 2);
    k_inproj<<<gip, IP_THREADS, smem_ip>>>(W_ih_f, b_f, W_ih_b, b_b);
    k_recur<<<2 * RBG * RUS, R_THREADS, smem_rc>>>(W_hh_f, W_hh_b);
    k_emit<<<SEQ, 256>>>(W_lin, b_lin);
    k_crf<<<NB, 32>>>(tags, trans, out);
}

// round 14
// speedup vs baseline: 1.1206x; 1.1206x over previous
#include <cuda_runtime.h>
#include <cstdint>
#include <math.h>

#define SEQ 256
#define NB 64
#define HID 300
#define G4 1200
#define NTAG 12

// recurrence: 2 dirs x 8 batch-groups x 8 unit-slices = 128 CTAs  (R10 core)
#define RBG 8
#define RUS 8
#define RBS 8
#define RUPC 38
#define R_P 76
#define R_KS 8
#define R_ACT 608
#define R_THREADS 640

// input projection: persistent weights; 7 seq-splits x 20 m x 2 dirs = 280 CTAs (one wave)
// s-blocked: 3 sequence positions per pass share each weight LDS
#define IP_MB 20
#define IP_ROWS 60
#define IP_THREADS 320
#define IP_JS 7
#define IP_SC 37
#define IP_KC 20
#define IP_NKC 15
#define IP_CHF (IP_KC * NB)       // 1280 floats per chunk per stream
#define IP_CH4 (IP_CHF / 4)       // 320 float4 per chunk per stream

// emissions: 4 s per CTA
#define EM_SPC 4

typedef unsigned long long ull;

__device__ __forceinline__ ull pack2(float lo, float hi) {
    ull r; asm("mov.b64 %0, {%1, %2};" : "=l"(r) : "f"(lo), "f"(hi)); return r;
}
__device__ __forceinline__ void unpack2(ull v, float& lo, float& hi) {
    asm("mov.b64 {%0, %1}, %2;" : "=f"(lo), "=f"(hi) : "l"(v));
}
__device__ __forceinline__ ull fma2(ull a, ull b, ull c) {
    ull d; asm("fma.rn.f32x2 %0, %1, %2, %3;" : "=l"(d) : "l"(a), "l"(b), "l"(c)); return d;
}
__device__ __forceinline__ ull add2(ull a, ull b) {
    ull d; asm("add.rn.f32x2 %0, %1, %2;" : "=l"(d) : "l"(a), "l"(b)); return d;
}
__device__ __forceinline__ float ftanh(float x) {
    float y; asm("tanh.approx.f32 %0, %1;" : "=f"(y) : "f"(x)); return y;
}
__device__ __forceinline__ float fsigm(float x) {
    return 0.5f * ftanh(0.5f * x) + 0.5f;
}
__device__ __forceinline__ uint32_t smem_u32_of(const void* p) {
    uint32_t a;
    asm("{ .reg .u64 t0; cvta.to.shared.u64 t0, %1; cvt.u32.u64 %0, t0; }" : "=r"(a) : "l"(p));
    return a;
}
__device__ __forceinline__ void cpasync16(uint32_t saddr, const void* g) {
    asm volatile("cp.async.cg.shared.global [%0], [%1], 16;" :: "r"(saddr), "l"(g));
}

// ---------------- scratch (device globals; no allocations) ----------------
__device__ float g_XT[SEQ * HID * NB];
__device__ float g_G[2][SEQ][G4 * NB];
__device__ float g_hall[2][SEQ][RBG * HID * RBS];
__device__ float g_emit[SEQ][NB][NTAG];
__device__ int   g_cnt2[16][32];

extern __shared__ float sm[];

// ---------------- embedding gather + transpose (+ counter reset) ----------------
__global__ void k_gather(const int* __restrict__ sent, const float* __restrict__ emb) {
    int s = blockIdx.x;
    __shared__ float sx[64][33];
    __shared__ int rows[64];
    int t = threadIdx.x;  // 256
    if (s == 0 && t < 16) g_cnt2[t][0] = 0;
    if (t < 64) rows[t] = sent[t * SEQ + s];
    __syncthreads();
    for (int kc = 0; kc < 10; kc++) {
        int kbase = kc * 32;
        int width = HID - kbase; if (width > 32) width = 32;
        int kk = t & 31, bg = t >> 5;
        if (kk < width) {
            for (int b = bg; b < 64; b += 8)
                sx[b][kk] = emb[rows[b] * HID + kbase + kk];
        }
        __syncthreads();
        int b = t & 63, kg = t >> 6;
        for (int k2 = kg; k2 < width; k2 += 4)
            g_XT[(s * HID + kbase + k2) * NB + b] = sx[b][k2];
        __syncthreads();
    }
}

// ---------------- input projection: persistent weights, s-blocked (3 s per pass) ----------------
__global__ void __launch_bounds__(IP_THREADS, 2) k_inproj(
    const float* __restrict__ Wf, const float* __restrict__ bf,
    const float* __restrict__ Wb, const float* __restrict__ bb)
{
    int j = blockIdx.x, m = blockIdx.y, d = blockIdx.z;
    const float* W    = d ? Wb : Wf;
    const float* bias = d ? bb : bf;
    float* ws = sm;                        // 18000 floats: ws[k*60 + r]
    float* xb = sm + HID * IP_ROWS;        // 6 x 1280 floats: [buf][stream]
    int t = threadIdx.x;
    int u0 = m * 15;

    int s0 = j * IP_SC;
    int ns = SEQ - s0; if (ns > IP_SC) ns = IP_SC;
    int ntrip = (ns + 2) / 3;
    int slast = s0 + ns - 1;

    uint32_t xb_u32 = smem_u32_of(xb);

    for (int idx = t; idx < HID * IP_ROWS; idx += IP_THREADS) {
        int k = idx / IP_ROWS, r = idx - k * IP_ROWS;
        int ul = r >> 2, gate = r & 3;
        ws[idx] = W[(gate * HID + u0 + ul) * HID + k];
    }

    int b = t & 63, rg = t >> 6;

    float bv[12];
    int rowv[12];
#pragma unroll
    for (int q = 0; q < 12; q++) {
        int r = rg * 12 + q;
        int row = (r & 3) * HID + u0 + (r >> 2);
        rowv[q] = row;
        bv[q] = bias[row];
    }
    __syncthreads();   // ws ready

    for (int tr = 0; tr < ntrip; tr++) {
        int sA = s0 + 3 * tr;
        int sB = sA + 1; if (sB > slast) sB = slast;
        int sC = sA + 2; if (sC > slast) sC = slast;
        const float4* gS[3];
        gS[0] = (const float4*)(g_XT + (long long)sA * (HID * NB));
        gS[1] = (const float4*)(g_XT + (long long)sB * (HID * NB));
        gS[2] = (const float4*)(g_XT + (long long)sC * (HID * NB));

#pragma unroll
        for (int q = 0; q < 3; q++) {
            uint32_t dst = xb_u32 + (q * IP_CHF + t * 4) * 4;
            cpasync16(dst, gS[q] + t);
        }
        asm volatile("cp.async.commit_group;");

        ull accA[6], accB[6], accC[6];
#pragma unroll
        for (int p = 0; p < 6; p++) { accA[p] = 0ull; accB[p] = 0ull; accC[p] = 0ull; }

        const ulonglong2* wp = ((const ulonglong2*)ws) + rg * 3;

        for (int kc = 0; kc < IP_NKC; kc++) {
            int cur = kc & 1;
            if (kc < IP_NKC - 1) {
                int nb4 = (kc + 1) * IP_CH4;
                uint32_t bufb = xb_u32 + ((kc + 1) & 1) * (3 * IP_CHF * 4);
#pragma unroll
                for (int q = 0; q < 3; q++) {
                    uint32_t dst = bufb + (q * IP_CHF + t * 4) * 4;
                    cpasync16(dst, gS[q] + nb4 + t);
                }
                asm volatile("cp.async.commit_group;");
                asm volatile("cp.async.wait_group 1;");
            } else {
                asm volatile("cp.async.wait_group 0;");
            }
            __syncthreads();

            const float* base = xb + cur * (3 * IP_CHF);
            const float* xpA = base + b;
            const float* xpB = base + IP_CHF + b;
            const float* xpC = base + 2 * IP_CHF + b;
#pragma unroll 5
            for (int k = 0; k < IP_KC; k++) {
                float xa = xpA[k * NB];
                float xv = xpB[k * NB];
                float xc = xpC[k * NB];
                ull h2a = pack2(xa, xa);
                ull h2b = pack2(xv, xv);
                ull h2c = pack2(xc, xc);
                ulonglong2 w0 = wp[0], w1 = wp[1], w2 = wp[2];
                accA[0] = fma2(w0.x, h2a, accA[0]); accB[0] = fma2(w0.x, h2b, accB[0]); accC[0] = fma2(w0.x, h2c, accC[0]);
                accA[1] = fma2(w0.y, h2a, accA[1]); accB[1] = fma2(w0.y, h2b, accB[1]); accC[1] = fma2(w0.y, h2c, accC[1]);
                accA[2] = fma2(w1.x, h2a, accA[2]); accB[2] = fma2(w1.x, h2b, accB[2]); accC[2] = fma2(w1.x, h2c, accC[2]);
                accA[3] = fma2(w1.y, h2a, accA[3]); accB[3] = fma2(w1.y, h2b, accB[3]); accC[3] = fma2(w1.y, h2c, accC[3]);
                accA[4] = fma2(w2.x, h2a, accA[4]); accB[4] = fma2(w2.x, h2b, accB[4]); accC[4] = fma2(w2.x, h2c, accC[4]);
                accA[5] = fma2(w2.y, h2a, accA[5]); accB[5] = fma2(w2.y, h2b, accB[5]); accC[5] = fma2(w2.y, h2c, accC[5]);
                wp += 15;
            }
            __syncthreads();
        }

        float* GdA = g_G[d][sA];
        float* GdB = g_G[d][sB];
        float* GdC = g_G[d][sC];
#pragma unroll
        for (int p = 0; p < 6; p++) {
            float a0, a1, b0, b1, c0x, c1x;
            unpack2(accA[p], a0, a1);
            unpack2(accB[p], b0, b1);
            unpack2(accC[p], c0x, c1x);
            int ra = rowv[2 * p], rb = rowv[2 * p + 1];
            GdA[ra * NB + b] = a0 + bv[2 * p];
            GdA[rb * NB + b] = a1 + bv[2 * p + 1];
            GdB[ra * NB + b] = b0 + bv[2 * p];
            GdB[rb * NB + b] = b1 + bv[2 * p + 1];
            GdC[ra * NB + b] = c0x + bv[2 * p];
            GdC[rb * NB + b] = c1x + bv[2 * p + 1];
        }
    }
}

// ---------------- persistent LSTM recurrence: 640 threads, 8-way k-split ----------------
// R12 structure with per-warp poll (no S1 CTA barrier; each warp acquires then stages).
__global__ void __launch_bounds__(R_THREADS, 1) k_recur(
    const float* __restrict__ Whf, const float* __restrict__ Whb)
{
    int bid = blockIdx.x;
    int d = bid >> 6;
    int g = (bid >> 3) & 7;
    int m = bid & 7;
    const float* W = d ? Whb : Whf;

    float* ws = sm;                    // ws[k*152 + r], row pairs packed as ull
    float* hs = sm + HID * 152;        // hs[k*8 + bo]
    ull*  red = (ull*)(hs + HID * RBS);   // 8 * 608 ull

    int t = threadIdx.x;
    int lane = t & 31;
    int u0 = m * RUPC;
    int cu = HID - u0; if (cu > RUPC) cu = RUPC;

    for (int idx = t; idx < HID * 152; idx += R_THREADS) {
        int k = idx / 152, r = idx - k * 152;
        int ul = r >> 2, gate = r & 3;
        ws[idx] = (ul < cu) ? W[(gate * HID + u0 + ul) * HID + k] : 0.f;
    }
    __syncthreads();

    int ks = t / R_P;                  // 0..7 active, 8 = spare warp
    int p  = t - ks * R_P;             // rowpair 0..75
    bool gemv = (t < R_ACT);
    int k0   = (ks < 4) ? 38 * ks : 152 + 37 * (ks - 4);
    int klen = (ks < 4) ? 38 : 37;
    if (!gemv) { k0 = 0; klen = 0; }
    int bp = (t < 304) ? ks : 0;
    int ul = p >> 1;
    bool doer = (t < 304) && ((p & 1) == 0) && (ul < cu);
    int boff = g * RBS + bp * 2;
    float c0 = 0.f, c1 = 0.f;
    int* cnt = &g_cnt2[d * 8 + g][0];
    const ull* wsu = (const ull*)ws;
    const ulonglong2* hsu = (const ulonglong2*)hs;

    for (int step = 0; step < SEQ; step++) {
        int pos = d ? (SEQ - 1 - step) : step;
        const float* Gp = g_G[d][pos];

        float2 Gv0, Gv1, Gv2, Gv3;
        if (doer) {
            int gb = (u0 + ul) * NB + boff;
            Gv0 = *(const float2*)(Gp + 0 * HID * NB + gb);
            Gv1 = *(const float2*)(Gp + 1 * HID * NB + gb);
            Gv2 = *(const float2*)(Gp + 2 * HID * NB + gb);
            Gv3 = *(const float2*)(Gp + 3 * HID * NB + gb);
        }

        float s0lo = 0.f, s0hi = 0.f, s1lo = 0.f, s1hi = 0.f;

        if (step > 0) {
            // per-warp poll: each warp's lane 0 acquires the counter, then the
            // warp proceeds straight to staging its own slice of h.
            {
                int target = RUS * step;
                if (lane == 0) {
                    int v;
                    do {
                        asm volatile("ld.acquire.gpu.global.b32 %0, [%1];" : "=r"(v) : "l"(cnt) : "memory");
                        if (v < target) __nanosleep(20);
                    } while (v < target);
                }
                __syncwarp();
            }

            {
                int prev = d ? (SEQ - step) : (step - 1);
                const float4* src = (const float4*)(g_hall[d][prev] + g * (HID * RBS));
                float4* dst = (float4*)hs;
                if (t < HID * RBS / 4) dst[t] = src[t];
            }
            __syncthreads();   // S2: hs staged (cross-warp)

            ull a00 = 0, a01 = 0, a02 = 0, a03 = 0;
            ull a10 = 0, a11 = 0, a12 = 0, a13 = 0;
#pragma unroll 2
            for (int kk = 0; kk < klen; kk++) {
                int k = k0 + kk;
                ull w = wsu[k * R_P + p];
                float w0, w1; unpack2(w, w0, w1);
                ull w00 = pack2(w0, w0), w11 = pack2(w1, w1);
                ulonglong2 hA = hsu[k * 2];
                ulonglong2 hB = hsu[k * 2 + 1];
                a00 = fma2(w00, hA.x, a00); a01 = fma2(w00, hA.y, a01);
                a02 = fma2(w00, hB.x, a02); a03 = fma2(w00, hB.y, a03);
                a10 = fma2(w11, hA.x, a10); a11 = fma2(w11, hA.y, a11);
                a12 = fma2(w11, hB.x, a12); a13 = fma2(w11, hB.y, a13);
            }
            if (gemv) {
                red[0 * R_ACT + t] = a00; red[1 * R_ACT + t] = a01;
                red[2 * R_ACT + t] = a02; red[3 * R_ACT + t] = a03;
                red[4 * R_ACT + t] = a10; red[5 * R_ACT + t] = a11;
                red[6 * R_ACT + t] = a12; red[7 * R_ACT + t] = a13;
            }
            __syncthreads();   // S3: partials visible

            if (t < 304) {
                const ull* r0 = red + bp * R_ACT + p;
                const ull* r1 = red + (4 + bp) * R_ACT + p;
                ull s0 = r0[0];
                ull s1 = r1[0];
#pragma unroll
                for (int q = 1; q < R_KS; q++) {
                    s0 = add2(s0, r0[q * R_P]);
                    s1 = add2(s1, r1[q * R_P]);
                }
                unpack2(s0, s0lo, s0hi);
                unpack2(s1, s1lo, s1hi);
            }
        }

        float g2lo = __shfl_down_sync(0xffffffffu, s0lo, 1);
        float g2hi = __shfl_down_sync(0xffffffffu, s0hi, 1);
        float g3lo = __shfl_down_sync(0xffffffffu, s1lo, 1);
        float g3hi = __shfl_down_sync(0xffffffffu, s1hi, 1);

        if (doer) {
            float i0 = fsigm(s0lo + Gv0.x), i1 = fsigm(s0hi + Gv0.y);
            float f0 = fsigm(s1lo + Gv1.x), f1 = fsigm(s1hi + Gv1.y);
            float q0 = ftanh(g2lo + Gv2.x), q1 = ftanh(g2hi + Gv2.y);
            float o0 = fsigm(g3lo + Gv3.x), o1 = fsigm(g3hi + Gv3.y);
            c0 = f0 * c0 + i0 * q0;
            c1 = f1 * c1 + i1 * q1;
            float2 hv;
            hv.x = o0 * ftanh(c0);
            hv.y = o1 * ftanh(c1);
            *(float2*)(g_hall[d][pos] + g * (HID * RBS) + (u0 + ul) * RBS + bp * 2) = hv;
        }

        __syncthreads();   // S6: h stores done before release
        if (t == 0)
            asm volatile("red.release.gpu.global.add.s32 [%0], 1;" :: "l"(cnt) : "memory");
    }
}

// ---------------- emissions: 4 s per CTA, weights staged once ----------------
__global__ void k_emit(const float* __restrict__ Wl, const float* __restrict__ bl) {
    int sc = blockIdx.x, t = threadIdx.x;  // 256
    __shared__ float wl[600 * NTAG];
    __shared__ float red2[4 * NTAG * NB];
    for (int idx = t; idx < 600 * NTAG; idx += 256) {
        int k = idx / NTAG, j = idx - k * NTAG;
        wl[idx] = Wl[j * 600 + k];
    }
    __syncthreads();
    int b = t & 63, ksx = t >> 6;
    int gof = (b >> 3) * (HID * RBS) + (b & 7);
    int k0 = ksx * 150;

    for (int si = 0; si < EM_SPC; si++) {
        int s = sc * EM_SPC + si;
        const float* hf = g_hall[0][s];
        const float* hb = g_hall[1][s];
        float acc[NTAG];
#pragma unroll
        for (int j = 0; j < NTAG; j++) acc[j] = 0.f;
        for (int k = k0; k < k0 + 150; k++) {
            float v = (k < HID) ? hf[gof + k * RBS] : hb[gof + (k - HID) * RBS];
            const float4* w4 = (const float4*)(wl + k * NTAG);
#pragma unroll
            for (int q = 0; q < 3; q++) {
                float4 w = w4[q];
                acc[4 * q + 0] += w.x * v; acc[4 * q + 1] += w.y * v;
                acc[4 * q + 2] += w.z * v; acc[4 * q + 3] += w.w * v;
            }
        }
#pragma unroll
        for (int j = 0; j < NTAG; j++) red2[(ksx * NTAG + j) * NB + b] = acc[j];
        __syncthreads();
        for (int idx = t; idx < NTAG * NB; idx += 256) {
            int j = idx >> 6, b2 = idx & 63;
            float v = red2[(0 * NTAG + j) * NB + b2] + red2[(1 * NTAG + j) * NB + b2]
                    + red2[(2 * NTAG + j) * NB + b2] + red2[(3 * NTAG + j) * NB + b2];
            g_emit[s][b2][j] = v + bl[j];
        }
        __syncthreads();   // red2 reads done before next s overwrites
    }
}

// ---------------- CRF forward + gold score + loss ----------------
__global__ void k_crf(const int* __restrict__ tags, const float* __restrict__ trans,
                      float* __restrict__ out) {
    int b = blockIdx.x;
    int j = threadIdx.x;
    float Tcol[NTAG];
#pragma unroll
    for (int i = 0; i < NTAG; i++) Tcol[i] = (j < NTAG) ? trans[i * NTAG + j] : 0.f;
    float dcur = (j < NTAG) ? g_emit[0][b][j] : -1e30f;

    float ts = 0.f;
    for (int s = j; s < SEQ; s += 32) {
        int tg = tags[b * SEQ + s];
        ts += g_emit[s][b][tg];
        if (s < SEQ - 1) ts += trans[tg * NTAG + tags[b * SEQ + s + 1]];
    }
#pragma unroll
    for (int off = 16; off; off >>= 1) ts += __shfl_xor_sync(0xffffffffu, ts, off);

    for (int s = 1; s < SEQ; s++) {
        float v[NTAG];
#pragma unroll
        for (int i = 0; i < NTAG; i++)
            v[i] = __shfl_sync(0xffffffffu, dcur, i) + Tcol[i];
        float mx = v[0];
#pragma unroll
        for (int i = 1; i < NTAG; i++) mx = fmaxf(mx, v[i]);
        float sum = 0.f;
#pragma unroll
        for (int i = 0; i < NTAG; i++) sum += expf(v[i] - mx);
        float e = (j < NTAG) ? g_emit[s][b][j] : 0.f;
        dcur = e + mx + logf(sum);
    }

    float dd = (j < NTAG) ? dcur : -1e30f;
    float mm = dd;
#pragma unroll
    for (int off = 16; off; off >>= 1) mm = fmaxf(mm, __shfl_xor_sync(0xffffffffu, mm, off));
    float se = (j < NTAG) ? expf(dd - mm) : 0.f;
#pragma unroll
    for (int off = 16; off; off >>= 1) se += __shfl_xor_sync(0xffffffffu, se, off);
    if (j == 0) out[b] = mm + logf(se) - ts;
}

// ---------------- launch ----------------
extern "C" void kernel_launch(void* const* d_in, const int* in_sizes, int n_in,
                              void* d_out, int out_size) {
    const int*   sentences = (const int*)d_in[0];
    const int*   tags      = (const int*)d_in[1];
    const float* emb       = (const float*)d_in[2];
    const float* W_ih_f    = (const float*)d_in[3];
    const float* W_hh_f    = (const float*)d_in[4];
    const float* b_f       = (const float*)d_in[5];
    const float* W_ih_b    = (const float*)d_in[6];
    const float* W_hh_b    = (const float*)d_in[7];
    const float* b_b       = (const float*)d_in[8];
    const float* W_lin     = (const float*)d_in[9];
    const float* b_lin     = (const float*)d_in[10];
    const float* trans     = (const float*)d_in[11];
    float* out = (float*)d_out;

    int smem_ip = (HID * IP_ROWS + 6 * IP_CHF) * 4;                   // 102720 B
    int smem_rc = (HID * 152 + HID * RBS) * 4 + R_KS * R_ACT * 8;     // 230912 B
    cudaFuncSetAttribute(k_inproj, cudaFuncAttributeMaxDynamicSharedMemorySize, smem_ip);
    cudaFuncSetAttribute(k_recur,  cudaFuncAttributeMaxDynamicSharedMemorySize, smem_rc);

    k_gather<<<SEQ, 256>>>(sentences, emb);
    dim3 gip(IP_JS, IP_MB, 2);
    k_inproj<<<gip, IP_THREADS, smem_ip>>>(W_ih_f, b_f, W_ih_b, b_b);
    k_recur<<<2 * RBG * RUS, R_THREADS, smem_rc>>>(W_hh_f, W_hh_b);
    k_emit<<<SEQ / EM_SPC, 256>>>(W_lin, b_lin);
    k_crf<<<NB, 32>>>(tags, trans, out);
}

// round 15
// speedup vs baseline: 1.1599x; 1.0351x over previous
#include <cuda_runtime.h>
#include <cstdint>
#include <math.h>

#define SEQ 256
#define NB 64
#define HID 300
#define G4 1200
#define NTAG 12

// recurrence: 2 dirs x 8 batch-groups x 8 unit-slices = 128 CTAs
// 768 threads = 8 k-groups x 96 (76 active GEMV lanes each, warp-aligned)
#define RBG 8
#define RUS 8
#define RBS 8
#define RUPC 38
#define R_P 76
#define R_KS 8
#define R_ACT 608
#define R_THREADS 768

// input projection: persistent weights; 7 seq-splits x 20 m x 2 dirs = 280 CTAs (one wave)
#define IP_MB 20
#define IP_ROWS 60
#define IP_THREADS 320
#define IP_JS 7
#define IP_SC 37
#define IP_KC 20
#define IP_NKC 15
#define IP_CHF (IP_KC * NB)
#define IP_CH4 (IP_CHF / 4)

typedef unsigned long long ull;

__device__ __forceinline__ ull pack2(float lo, float hi) {
    ull r; asm("mov.b64 %0, {%1, %2};" : "=l"(r) : "f"(lo), "f"(hi)); return r;
}
__device__ __forceinline__ void unpack2(ull v, float& lo, float& hi) {
    asm("mov.b64 {%0, %1}, %2;" : "=f"(lo), "=f"(hi) : "l"(v));
}
__device__ __forceinline__ ull fma2(ull a, ull b, ull c) {
    ull d; asm("fma.rn.f32x2 %0, %1, %2, %3;" : "=l"(d) : "l"(a), "l"(b), "l"(c)); return d;
}
__device__ __forceinline__ ull add2(ull a, ull b) {
    ull d; asm("add.rn.f32x2 %0, %1, %2;" : "=l"(d) : "l"(a), "l"(b)); return d;
}
__device__ __forceinline__ float ftanh(float x) {
    float y; asm("tanh.approx.f32 %0, %1;" : "=f"(y) : "f"(x)); return y;
}
__device__ __forceinline__ float fsigm(float x) {
    return 0.5f * ftanh(0.5f * x) + 0.5f;
}
__device__ __forceinline__ uint32_t smem_u32_of(const void* p) {
    uint32_t a;
    asm("{ .reg .u64 t0; cvta.to.shared.u64 t0, %1; cvt.u32.u64 %0, t0; }" : "=r"(a) : "l"(p));
    return a;
}
__device__ __forceinline__ void cpasync16(uint32_t saddr, const void* g) {
    asm volatile("cp.async.cg.shared.global [%0], [%1], 16;" :: "r"(saddr), "l"(g));
}

// ---------------- scratch (device globals; no allocations) ----------------
__device__ float g_XT[SEQ * HID * NB];
__device__ float g_G[2][SEQ][G4 * NB];
__device__ float g_hall[2][SEQ][RBG * HID * RBS];
__device__ float g_emit[SEQ][NB][NTAG];
__device__ int   g_cnt3[2][RBG][RUS][32];   // per (dir,group,producer) counters, 128B padded

extern __shared__ float sm[];

// ---------------- embedding gather + transpose (+ counter reset) ----------------
__global__ void k_gather(const int* __restrict__ sent, const float* __restrict__ emb) {
    int s = blockIdx.x;
    __shared__ float sx[64][33];
    __shared__ int rows[64];
    int t = threadIdx.x;  // 256
    if (s == 0 && t < 128) g_cnt3[t >> 6][(t >> 3) & 7][t & 7][0] = 0;
    if (t < 64) rows[t] = sent[t * SEQ + s];
    __syncthreads();
    for (int kc = 0; kc < 10; kc++) {
        int kbase = kc * 32;
        int width = HID - kbase; if (width > 32) width = 32;
        int kk = t & 31, bg = t >> 5;
        if (kk < width) {
            for (int b = bg; b < 64; b += 8)
                sx[b][kk] = emb[rows[b] * HID + kbase + kk];
        }
        __syncthreads();
        int b = t & 63, kg = t >> 6;
        for (int k2 = kg; k2 < width; k2 += 4)
            g_XT[(s * HID + kbase + k2) * NB + b] = sx[b][k2];
        __syncthreads();
    }
}

// ---------------- input projection: persistent weights, s-blocked (3 s per pass) ----------------
__global__ void __launch_bounds__(IP_THREADS, 2) k_inproj(
    const float* __restrict__ Wf, const float* __restrict__ bf,
    const float* __restrict__ Wb, const float* __restrict__ bb)
{
    int j = blockIdx.x, m = blockIdx.y, d = blockIdx.z;
    const float* W    = d ? Wb : Wf;
    const float* bias = d ? bb : bf;
    float* ws = sm;
    float* xb = sm + HID * IP_ROWS;
    int t = threadIdx.x;
    int u0 = m * 15;

    int s0 = j * IP_SC;
    int ns = SEQ - s0; if (ns > IP_SC) ns = IP_SC;
    int ntrip = (ns + 2) / 3;
    int slast = s0 + ns - 1;

    uint32_t xb_u32 = smem_u32_of(xb);

    for (int idx = t; idx < HID * IP_ROWS; idx += IP_THREADS) {
        int k = idx / IP_ROWS, r = idx - k * IP_ROWS;
        int ul = r >> 2, gate = r & 3;
        ws[idx] = W[(gate * HID + u0 + ul) * HID + k];
    }

    int b = t & 63, rg = t >> 6;

    float bv[12];
    int rowv[12];
#pragma unroll
    for (int q = 0; q < 12; q++) {
        int r = rg * 12 + q;
        int row = (r & 3) * HID + u0 + (r >> 2);
        rowv[q] = row;
        bv[q] = bias[row];
    }
    __syncthreads();

    for (int tr = 0; tr < ntrip; tr++) {
        int sA = s0 + 3 * tr;
        int sB = sA + 1; if (sB > slast) sB = slast;
        int sC = sA + 2; if (sC > slast) sC = slast;
        const float4* gS[3];
        gS[0] = (const float4*)(g_XT + (long long)sA * (HID * NB));
        gS[1] = (const float4*)(g_XT + (long long)sB * (HID * NB));
        gS[2] = (const float4*)(g_XT + (long long)sC * (HID * NB));

#pragma unroll
        for (int q = 0; q < 3; q++) {
            uint32_t dst = xb_u32 + (q * IP_CHF + t * 4) * 4;
            cpasync16(dst, gS[q] + t);
        }
        asm volatile("cp.async.commit_group;");

        ull accA[6], accB[6], accC[6];
#pragma unroll
        for (int p = 0; p < 6; p++) { accA[p] = 0ull; accB[p] = 0ull; accC[p] = 0ull; }

        const ulonglong2* wp = ((const ulonglong2*)ws) + rg * 3;

        for (int kc = 0; kc < IP_NKC; kc++) {
            int cur = kc & 1;
            if (kc < IP_NKC - 1) {
                int nb4 = (kc + 1) * IP_CH4;
                uint32_t bufb = xb_u32 + ((kc + 1) & 1) * (3 * IP_CHF * 4);
#pragma unroll
                for (int q = 0; q < 3; q++) {
                    uint32_t dst = bufb + (q * IP_CHF + t * 4) * 4;
                    cpasync16(dst, gS[q] + nb4 + t);
                }
                asm volatile("cp.async.commit_group;");
                asm volatile("cp.async.wait_group 1;");
            } else {
                asm volatile("cp.async.wait_group 0;");
            }
            __syncthreads();

            const float* base = xb + cur * (3 * IP_CHF);
            const float* xpA = base + b;
            const float* xpB = base + IP_CHF + b;
            const float* xpC = base + 2 * IP_CHF + b;
#pragma unroll 5
            for (int k = 0; k < IP_KC; k++) {
                float xa = xpA[k * NB];
                float xv = xpB[k * NB];
                float xc = xpC[k * NB];
                ull h2a = pack2(xa, xa);
                ull h2b = pack2(xv, xv);
                ull h2c = pack2(xc, xc);
                ulonglong2 w0 = wp[0], w1 = wp[1], w2 = wp[2];
                accA[0] = fma2(w0.x, h2a, accA[0]); accB[0] = fma2(w0.x, h2b, accB[0]); accC[0] = fma2(w0.x, h2c, accC[0]);
                accA[1] = fma2(w0.y, h2a, accA[1]); accB[1] = fma2(w0.y, h2b, accB[1]); accC[1] = fma2(w0.y, h2c, accC[1]);
                accA[2] = fma2(w1.x, h2a, accA[2]); accB[2] = fma2(w1.x, h2b, accB[2]); accC[2] = fma2(w1.x, h2c, accC[2]);
                accA[3] = fma2(w1.y, h2a, accA[3]); accB[3] = fma2(w1.y, h2b, accB[3]); accC[3] = fma2(w1.y, h2c, accC[3]);
                accA[4] = fma2(w2.x, h2a, accA[4]); accB[4] = fma2(w2.x, h2b, accB[4]); accC[4] = fma2(w2.x, h2c, accC[4]);
                accA[5] = fma2(w2.y, h2a, accA[5]); accB[5] = fma2(w2.y, h2b, accB[5]); accC[5] = fma2(w2.y, h2c, accC[5]);
                wp += 15;
            }
            __syncthreads();
        }

        float* GdA = g_G[d][sA];
        float* GdB = g_G[d][sB];
        float* GdC = g_G[d][sC];
#pragma unroll
        for (int p = 0; p < 6; p++) {
            float a0, a1, b0, b1, c0x, c1x;
            unpack2(accA[p], a0, a1);
            unpack2(accB[p], b0, b1);
            unpack2(accC[p], c0x, c1x);
            int ra = rowv[2 * p], rb = rowv[2 * p + 1];
            GdA[ra * NB + b] = a0 + bv[2 * p];
            GdA[rb * NB + b] = a1 + bv[2 * p + 1];
            GdB[ra * NB + b] = b0 + bv[2 * p];
            GdB[rb * NB + b] = b1 + bv[2 * p + 1];
            GdC[ra * NB + b] = c0x + bv[2 * p];
            GdC[rb * NB + b] = c1x + bv[2 * p + 1];
        }
    }
}

// ---------------- persistent LSTM recurrence: point-to-point producer flags ----------------
// 768 threads = 8 groups x 96. Group q owns k range = producer CTA q's unit slice
// ([38q, 38q+38), last 34). Each group polls ONLY its producer's counter, stages its own
// 1.2KB h slice, group-barriers (3 warps), and runs its GEMV — no CTA-wide wait on the
// slowest producer until the reduce. Phase-2/gates mapping identical to R12.
__global__ void __launch_bounds__(R_THREADS, 1) k_recur(
    const float* __restrict__ Whf, const float* __restrict__ Whb)
{
    int bid = blockIdx.x;
    int d = bid >> 6;
    int g = (bid >> 3) & 7;
    int m = bid & 7;
    const float* W = d ? Whb : Whf;

    float* ws = sm;                       // ws[k*152 + r], row pairs packed as ull
    float* hs = sm + HID * 152;           // hs[k*8 + bo]
    ull*  red = (ull*)(hs + HID * RBS);   // 8 * 608 ull

    int t = threadIdx.x;
    int lane = t & 31;
    int u0 = m * RUPC;
    int cu = HID - u0; if (cu > RUPC) cu = RUPC;

    for (int idx = t; idx < HID * 152; idx += R_THREADS) {
        int k = idx / 152, r = idx - k * 152;
        int ul = r >> 2, gate = r & 3;
        ws[idx] = (ul < cu) ? W[(gate * HID + u0 + ul) * HID + k] : 0.f;
    }
    __syncthreads();

    int gq = t / 96;               // k-group 0..7 (= producer index it depends on)
    int gp = t - gq * 96;          // pos in group; GEMV active for gp<76
    bool gemv = gp < R_P;
    int k0   = 38 * gq;
    int klen = (gq == 7) ? 34 : 38;
    int kl4  = (gq == 7) ? 68 : 76;    // float4 count of this group's h slice
    if (!gemv) klen = 0;
    int gpc = gemv ? gp : 0;

    // phase2 / gates mapping (identical to R12)
    int bp = (t < 304) ? (t / R_P) : 0;
    int pp = (t < 304) ? (t % R_P) : 0;
    int ul = pp >> 1;
    bool doer = (t < 304) && ((pp & 1) == 0) && (ul < cu);
    int boff = g * RBS + bp * 2;
    float c0 = 0.f, c1 = 0.f;
    int* mycnt = &g_cnt3[d][g][m][0];
    const int* prodcnt = &g_cnt3[d][g][gq][0];
    const ull* wsu = (const ull*)ws;
    const ulonglong2* hsu = (const ulonglong2*)hs;

    for (int step = 0; step < SEQ; step++) {
        int pos = d ? (SEQ - 1 - step) : step;
        const float* Gp = g_G[d][pos];

        float2 Gv0, Gv1, Gv2, Gv3;
        if (doer) {
            int gb = (u0 + ul) * NB + boff;
            Gv0 = *(const float2*)(Gp + 0 * HID * NB + gb);
            Gv1 = *(const float2*)(Gp + 1 * HID * NB + gb);
            Gv2 = *(const float2*)(Gp + 2 * HID * NB + gb);
            Gv3 = *(const float2*)(Gp + 3 * HID * NB + gb);
        }

        float s0lo = 0.f, s0hi = 0.f, s1lo = 0.f, s1hi = 0.f;

        if (step > 0) {
            // each warp's lane 0 polls ONLY the producer this group consumes
            if (lane == 0) {
                int v;
                do {
                    asm volatile("ld.acquire.gpu.global.b32 %0, [%1];" : "=r"(v) : "l"(prodcnt) : "memory");
                    if (v < step) __nanosleep(20);
                } while (v < step);
            }
            __syncwarp();

            // stage this group's own h slice (1.2KB; thread gp stages float4 gq*76+gp)
            {
                int prev = d ? (SEQ - step) : (step - 1);
                const float4* src = (const float4*)(g_hall[d][prev] + g * (HID * RBS));
                float4* dst = (float4*)hs;
                int f4 = gq * R_P + gp;
                if (gp < kl4) dst[f4] = src[f4];
            }
            // group barrier: the 3 warps of group gq (barrier id gq+1, 96 threads)
            asm volatile("bar.sync %0, %1;" :: "r"(gq + 1), "r"(96) : "memory");

            // partial GEMV over this group's k range
            ull a00 = 0, a01 = 0, a02 = 0, a03 = 0;
            ull a10 = 0, a11 = 0, a12 = 0, a13 = 0;
#pragma unroll 2
            for (int kk = 0; kk < klen; kk++) {
                int k = k0 + kk;
                ull w = wsu[k * R_P + gpc];
                float w0, w1; unpack2(w, w0, w1);
                ull w00 = pack2(w0, w0), w11 = pack2(w1, w1);
                ulonglong2 hA = hsu[k * 2];
                ulonglong2 hB = hsu[k * 2 + 1];
                a00 = fma2(w00, hA.x, a00); a01 = fma2(w00, hA.y, a01);
                a02 = fma2(w00, hB.x, a02); a03 = fma2(w00, hB.y, a03);
                a10 = fma2(w11, hA.x, a10); a11 = fma2(w11, hA.y, a11);
                a12 = fma2(w11, hB.x, a12); a13 = fma2(w11, hB.y, a13);
            }
            if (gemv) {
                int gi = gq * R_P + gp;    // compact slot 0..607 (same layout as R12)
                red[0 * R_ACT + gi] = a00; red[1 * R_ACT + gi] = a01;
                red[2 * R_ACT + gi] = a02; red[3 * R_ACT + gi] = a03;
                red[4 * R_ACT + gi] = a10; red[5 * R_ACT + gi] = a11;
                red[6 * R_ACT + gi] = a12; red[7 * R_ACT + gi] = a13;
            }
            __syncthreads();   // S3: all groups' partials visible

            if (t < 304) {
                const ull* r0 = red + bp * R_ACT + pp;
                const ull* r1 = red + (4 + bp) * R_ACT + pp;
                ull s0 = r0[0];
                ull s1 = r1[0];
#pragma unroll
                for (int q = 1; q < R_KS; q++) {
                    s0 = add2(s0, r0[q * R_P]);
                    s1 = add2(s1, r1[q * R_P]);
                }
                unpack2(s0, s0lo, s0hi);
                unpack2(s1, s1lo, s1hi);
            }
        }

        // exchange: even-pp thread (gates i,f) pulls gates g,o from odd partner (t+1)
        float g2lo = __shfl_down_sync(0xffffffffu, s0lo, 1);
        float g2hi = __shfl_down_sync(0xffffffffu, s0hi, 1);
        float g3lo = __shfl_down_sync(0xffffffffu, s1lo, 1);
        float g3hi = __shfl_down_sync(0xffffffffu, s1hi, 1);

        if (doer) {
            float i0 = fsigm(s0lo + Gv0.x), i1 = fsigm(s0hi + Gv0.y);
            float f0 = fsigm(s1lo + Gv1.x), f1 = fsigm(s1hi + Gv1.y);
            float q0 = ftanh(g2lo + Gv2.x), q1 = ftanh(g2hi + Gv2.y);
            float o0 = fsigm(g3lo + Gv3.x), o1 = fsigm(g3hi + Gv3.y);
            c0 = f0 * c0 + i0 * q0;
            c1 = f1 * c1 + i1 * q1;
            float2 hv;
            hv.x = o0 * ftanh(c0);
            hv.y = o1 * ftanh(c1);
            *(float2*)(g_hall[d][pos] + g * (HID * RBS) + (u0 + ul) * RBS + bp * 2) = hv;
        }

        __syncthreads();   // S6: this CTA's h slice fully stored
        if (t == 0)
            asm volatile("red.release.gpu.global.add.s32 [%0], 1;" :: "l"(mycnt) : "memory");
    }
}

// ---------------- emissions (R12 form: one s per CTA) ----------------
__global__ void k_emit(const float* __restrict__ Wl, const float* __restrict__ bl) {
    int s = blockIdx.x, t = threadIdx.x;  // 256
    __shared__ float wl[600 * NTAG];
    __shared__ float red2[4 * NTAG * NB];
    for (int idx = t; idx < 600 * NTAG; idx += 256) {
        int k = idx / NTAG, j = idx - k * NTAG;
        wl[idx] = Wl[j * 600 + k];
    }
    __syncthreads();
    int b = t & 63, ksx = t >> 6;
    int gof = (b >> 3) * (HID * RBS) + (b & 7);
    float acc[NTAG];
#pragma unroll
    for (int j = 0; j < NTAG; j++) acc[j] = 0.f;
    const float* hf = g_hall[0][s];
    const float* hb = g_hall[1][s];
    int k0 = ksx * 150;
    for (int k = k0; k < k0 + 150; k++) {
        float v = (k < HID) ? hf[gof + k * RBS] : hb[gof + (k - HID) * RBS];
        const float4* w4 = (const float4*)(wl + k * NTAG);
#pragma unroll
        for (int q = 0; q < 3; q++) {
            float4 w = w4[q];
            acc[4 * q + 0] += w.x * v; acc[4 * q + 1] += w.y * v;
            acc[4 * q + 2] += w.z * v; acc[4 * q + 3] += w.w * v;
        }
    }
#pragma unroll
    for (int j = 0; j < NTAG; j++) red2[(ksx * NTAG + j) * NB + b] = acc[j];
    __syncthreads();
    for (int idx = t; idx < NTAG * NB; idx += 256) {
        int j = idx >> 6, b2 = idx & 63;
        float v = red2[(0 * NTAG + j) * NB + b2] + red2[(1 * NTAG + j) * NB + b2]
                + red2[(2 * NTAG + j) * NB + b2] + red2[(3 * NTAG + j) * NB + b2];
        g_emit[s][b2][j] = v + bl[j];
    }
}

// ---------------- CRF forward + gold score + loss ----------------
__global__ void k_crf(const int* __restrict__ tags, const float* __restrict__ trans,
                      float* __restrict__ out) {
    int b = blockIdx.x;
    int j = threadIdx.x;
    float Tcol[NTAG];
#pragma unroll
    for (int i = 0; i < NTAG; i++) Tcol[i] = (j < NTAG) ? trans[i * NTAG + j] : 0.f;
    float dcur = (j < NTAG) ? g_emit[0][b][j] : -1e30f;

    float ts = 0.f;
    for (int s = j; s < SEQ; s += 32) {
        int tg = tags[b * SEQ + s];
        ts += g_emit[s][b][tg];
        if (s < SEQ - 1) ts += trans[tg * NTAG + tags[b * SEQ + s + 1]];
    }
#pragma unroll
    for (int off = 16; off; off >>= 1) ts += __shfl_xor_sync(0xffffffffu, ts, off);

    for (int s = 1; s < SEQ; s++) {
        float v[NTAG];
#pragma unroll
        for (int i = 0; i < NTAG; i++)
            v[i] = __shfl_sync(0xffffffffu, dcur, i) + Tcol[i];
        float mx = v[0];
#pragma unroll
        for (int i = 1; i < NTAG; i++) mx = fmaxf(mx, v[i]);
        float sum = 0.f;
#pragma unroll
        for (int i = 0; i < NTAG; i++) sum += expf(v[i] - mx);
        float e = (j < NTAG) ? g_emit[s][b][j] : 0.f;
        dcur = e + mx + logf(sum);
    }

    float dd = (j < NTAG) ? dcur : -1e30f;
    float mm = dd;
#pragma unroll
    for (int off = 16; off; off >>= 1) mm = fmaxf(mm, __shfl_xor_sync(0xffffffffu, mm, off));
    float se = (j < NTAG) ? expf(dd - mm) : 0.f;
#pragma unroll
    for (int off = 16; off; off >>= 1) se += __shfl_xor_sync(0xffffffffu, se, off);
    if (j == 0) out[b] = mm + logf(se) - ts;
}

// ---------------- launch ----------------
extern "C" void kernel_launch(void* const* d_in, const int* in_sizes, int n_in,
                              void* d_out, int out_size) {
    const int*   sentences = (const int*)d_in[0];
    const int*   tags      = (const int*)d_in[1];
    const float* emb       = (const float*)d_in[2];
    const float* W_ih_f    = (const float*)d_in[3];
    const float* W_hh_f    = (const float*)d_in[4];
    const float* b_f       = (const float*)d_in[5];
    const float* W_ih_b    = (const float*)d_in[6];
    const float* W_hh_b    = (const float*)d_in[7];
    const float* b_b       = (const float*)d_in[8];
    const float* W_lin     = (const float*)d_in[9];
    const float* b_lin     = (const float*)d_in[10];
    const float* trans     = (const float*)d_in[11];
    float* out = (float*)d_out;

    int smem_ip = (HID * IP_ROWS + 6 * IP_CHF) * 4;                   // 102720 B
    int smem_rc = (HID * 152 + HID * RBS) * 4 + R_KS * R_ACT * 8;     // 230912 B
    cudaFuncSetAttribute(k_inproj, cudaFuncAttributeMaxDynamicSharedMemorySize, smem_ip);
    cudaFuncSetAttribute(k_recur,  cudaFuncAttributeMaxDynamicSharedMemorySize, smem_rc);

    k_gather<<<SEQ, 256>>>(sentences, emb);
    dim3 gip(IP_JS, IP_MB, 2);
    k_inproj<<<gip, IP_THREADS, smem_ip>>>(W_ih_f, b_f, W_ih_b, b_b);
    k_recur<<<2 * RBG * RUS, R_THREADS, smem_rc>>>(W_hh_f, W_hh_b);
    k_emit<<<SEQ, 256>>>(W_lin, b_lin);
    k_crf<<<NB, 32>>>(tags, trans, out);
}

// round 16
// speedup vs baseline: 1.1904x; 1.0262x over previous
#include <cuda_runtime.h>
#include <cstdint>
#include <math.h>

#define SEQ 256
#define NB 64
#define HID 300
#define G4 1200
#define NTAG 12

// recurrence: 2 dirs x 8 batch-groups x 8 unit-slices = 128 CTAs  (R10/R12 config — best)
#define RBG 8
#define RUS 8
#define RBS 8
#define RUPC 38
#define R_P 76
#define R_KS 8
#define R_ACT 608
#define R_THREADS 640

// input projection: persistent weights; 7 seq-splits x 20 m x 2 dirs = 280 CTAs (one wave)
// s-blocked: 4 sequence positions per pass share each weight LDS
#define IP_MB 20
#define IP_ROWS 60
#define IP_THREADS 320
#define IP_JS 7
#define IP_SC 37
#define IP_KC 15
#define IP_NKC 20
#define IP_CHF (IP_KC * NB)       // 960 floats per chunk per stream
#define IP_CH4 (IP_CHF / 4)       // 240 float4 per chunk per stream

typedef unsigned long long ull;

__device__ __forceinline__ ull pack2(float lo, float hi) {
    ull r; asm("mov.b64 %0, {%1, %2};" : "=l"(r) : "f"(lo), "f"(hi)); return r;
}
__device__ __forceinline__ void unpack2(ull v, float& lo, float& hi) {
    asm("mov.b64 {%0, %1}, %2;" : "=f"(lo), "=f"(hi) : "l"(v));
}
__device__ __forceinline__ ull fma2(ull a, ull b, ull c) {
    ull d; asm("fma.rn.f32x2 %0, %1, %2, %3;" : "=l"(d) : "l"(a), "l"(b), "l"(c)); return d;
}
__device__ __forceinline__ ull add2(ull a, ull b) {
    ull d; asm("add.rn.f32x2 %0, %1, %2;" : "=l"(d) : "l"(a), "l"(b)); return d;
}
__device__ __forceinline__ float ftanh(float x) {
    float y; asm("tanh.approx.f32 %0, %1;" : "=f"(y) : "f"(x)); return y;
}
__device__ __forceinline__ float fsigm(float x) {
    return 0.5f * ftanh(0.5f * x) + 0.5f;
}
__device__ __forceinline__ uint32_t smem_u32_of(const void* p) {
    uint32_t a;
    asm("{ .reg .u64 t0; cvta.to.shared.u64 t0, %1; cvt.u32.u64 %0, t0; }" : "=r"(a) : "l"(p));
    return a;
}
__device__ __forceinline__ void cpasync16(uint32_t saddr, const void* g) {
    asm volatile("cp.async.cg.shared.global [%0], [%1], 16;" :: "r"(saddr), "l"(g));
}

// ---------------- scratch (device globals; no allocations) ----------------
__device__ float g_XT[SEQ * HID * NB];
__device__ float g_G[2][SEQ][G4 * NB];
__device__ float g_hall[2][SEQ][RBG * HID * RBS];
__device__ float g_emit[SEQ][NB][NTAG];
__device__ int   g_cnt2[16][32];            // per (dir,group) counters, 128B padded

extern __shared__ float sm[];

// ---------------- embedding gather + transpose (+ counter reset) ----------------
__global__ void k_gather(const int* __restrict__ sent, const float* __restrict__ emb) {
    int s = blockIdx.x;
    __shared__ float sx[64][33];
    __shared__ int rows[64];
    int t = threadIdx.x;  // 256
    if (s == 0 && t < 16) g_cnt2[t][0] = 0;
    if (t < 64) rows[t] = sent[t * SEQ + s];
    __syncthreads();
    for (int kc = 0; kc < 10; kc++) {
        int kbase = kc * 32;
        int width = HID - kbase; if (width > 32) width = 32;
        int kk = t & 31, bg = t >> 5;
        if (kk < width) {
            for (int b = bg; b < 64; b += 8)
                sx[b][kk] = emb[rows[b] * HID + kbase + kk];
        }
        __syncthreads();
        int b = t & 63, kg = t >> 6;
        for (int k2 = kg; k2 < width; k2 += 4)
            g_XT[(s * HID + kbase + k2) * NB + b] = sx[b][k2];
        __syncthreads();
    }
}

// ---------------- input projection: persistent weights, s-blocked (4 s per pass) ----------------
// CTA = (j, m, d): 60 gate rows; s in [j*37, ...) processed in quads sharing weight LDS.
// x streamed via cp.async double buffering (4 streams x 2 buffers x 15k-chunks).
__global__ void __launch_bounds__(IP_THREADS, 2) k_inproj(
    const float* __restrict__ Wf, const float* __restrict__ bf,
    const float* __restrict__ Wb, const float* __restrict__ bb)
{
    int j = blockIdx.x, m = blockIdx.y, d = blockIdx.z;
    const float* W    = d ? Wb : Wf;
    const float* bias = d ? bb : bf;
    float* ws = sm;                        // 18000 floats: ws[k*60 + r]
    float* xb = sm + HID * IP_ROWS;        // 2 bufs x 4 streams x 960 floats
    int t = threadIdx.x;
    int u0 = m * 15;

    int s0 = j * IP_SC;
    int ns = SEQ - s0; if (ns > IP_SC) ns = IP_SC;
    int nquad = (ns + 3) >> 2;
    int slast = s0 + ns - 1;

    uint32_t xb_u32 = smem_u32_of(xb);

    // stage weights once: ws[k*60 + r], r = ul*4 + gate, row = gate*300 + u0 + ul
    for (int idx = t; idx < HID * IP_ROWS; idx += IP_THREADS) {
        int k = idx / IP_ROWS, r = idx - k * IP_ROWS;
        int ul = r >> 2, gate = r & 3;
        ws[idx] = W[(gate * HID + u0 + ul) * HID + k];
    }

    int b = t & 63, rg = t >> 6;   // rg 0..4, owns rows rg*12 .. rg*12+11

    float bv[12];
    int rowv[12];
#pragma unroll
    for (int q = 0; q < 12; q++) {
        int r = rg * 12 + q;
        int row = (r & 3) * HID + u0 + (r >> 2);
        rowv[q] = row;
        bv[q] = bias[row];
    }
    __syncthreads();   // ws ready

    for (int qd = 0; qd < nquad; qd++) {
        int sA = s0 + 4 * qd;
        int sB = sA + 1; if (sB > slast) sB = slast;
        int sC = sA + 2; if (sC > slast) sC = slast;
        int sD = sA + 3; if (sD > slast) sD = slast;
        const float4* gS[4];
        gS[0] = (const float4*)(g_XT + (long long)sA * (HID * NB));
        gS[1] = (const float4*)(g_XT + (long long)sB * (HID * NB));
        gS[2] = (const float4*)(g_XT + (long long)sC * (HID * NB));
        gS[3] = (const float4*)(g_XT + (long long)sD * (HID * NB));

        // prefetch chunk 0 into buffer 0: 960 float4 total, 3 per thread
#pragma unroll
        for (int q = 0; q < 3; q++) {
            int gi = t + q * IP_THREADS;         // 0..959
            int st = gi / IP_CH4;                // stream 0..3
            int ix = gi - st * IP_CH4;           // float4 idx in stream
            uint32_t dst = xb_u32 + (st * IP_CHF + ix * 4) * 4;
            cpasync16(dst, gS[st] + ix);
        }
        asm volatile("cp.async.commit_group;");

        ull accA[6], accB[6], accC[6], accD[6];
#pragma unroll
        for (int p = 0; p < 6; p++) { accA[p] = 0ull; accB[p] = 0ull; accC[p] = 0ull; accD[p] = 0ull; }

        const ulonglong2* wp = ((const ulonglong2*)ws) + rg * 3;

        for (int kc = 0; kc < IP_NKC; kc++) {
            int cur = kc & 1;
            if (kc < IP_NKC - 1) {
                int nb4 = (kc + 1) * IP_CH4;
                uint32_t bufb = xb_u32 + ((kc + 1) & 1) * (4 * IP_CHF * 4);
#pragma unroll
                for (int q = 0; q < 3; q++) {
                    int gi = t + q * IP_THREADS;
                    int st = gi / IP_CH4;
                    int ix = gi - st * IP_CH4;
                    uint32_t dst = bufb + (st * IP_CHF + ix * 4) * 4;
                    cpasync16(dst, gS[st] + nb4 + ix);
                }
                asm volatile("cp.async.commit_group;");
                asm volatile("cp.async.wait_group 1;");
            } else {
                asm volatile("cp.async.wait_group 0;");
            }
            __syncthreads();   // current chunk visible

            const float* base = xb + cur * (4 * IP_CHF);
            const float* xpA = base + b;
            const float* xpB = base + IP_CHF + b;
            const float* xpC = base + 2 * IP_CHF + b;
            const float* xpD = base + 3 * IP_CHF + b;
#pragma unroll 5
            for (int k = 0; k < IP_KC; k++) {
                float xa = xpA[k * NB];
                float xv = xpB[k * NB];
                float xc = xpC[k * NB];
                float xd = xpD[k * NB];
                ull h2a = pack2(xa, xa);
                ull h2b = pack2(xv, xv);
                ull h2c = pack2(xc, xc);
                ull h2d = pack2(xd, xd);
                ulonglong2 w0 = wp[0], w1 = wp[1], w2 = wp[2];
                accA[0] = fma2(w0.x, h2a, accA[0]); accB[0] = fma2(w0.x, h2b, accB[0]);
                accC[0] = fma2(w0.x, h2c, accC[0]); accD[0] = fma2(w0.x, h2d, accD[0]);
                accA[1] = fma2(w0.y, h2a, accA[1]); accB[1] = fma2(w0.y, h2b, accB[1]);
                accC[1] = fma2(w0.y, h2c, accC[1]); accD[1] = fma2(w0.y, h2d, accD[1]);
                accA[2] = fma2(w1.x, h2a, accA[2]); accB[2] = fma2(w1.x, h2b, accB[2]);
                accC[2] = fma2(w1.x, h2c, accC[2]); accD[2] = fma2(w1.x, h2d, accD[2]);
                accA[3] = fma2(w1.y, h2a, accA[3]); accB[3] = fma2(w1.y, h2b, accB[3]);
                accC[3] = fma2(w1.y, h2c, accC[3]); accD[3] = fma2(w1.y, h2d, accD[3]);
                accA[4] = fma2(w2.x, h2a, accA[4]); accB[4] = fma2(w2.x, h2b, accB[4]);
                accC[4] = fma2(w2.x, h2c, accC[4]); accD[4] = fma2(w2.x, h2d, accD[4]);
                accA[5] = fma2(w2.y, h2a, accA[5]); accB[5] = fma2(w2.y, h2b, accB[5]);
                accC[5] = fma2(w2.y, h2c, accC[5]); accD[5] = fma2(w2.y, h2d, accD[5]);
                wp += 15;  // 60 floats per k
            }
            __syncthreads();   // reads done before this buffer is refilled
        }

        float* GdA = g_G[d][sA];
        float* GdB = g_G[d][sB];
        float* GdC = g_G[d][sC];
        float* GdD = g_G[d][sD];
#pragma unroll
        for (int p = 0; p < 6; p++) {
            float a0, a1, b0, b1, c0x, c1x, d0, d1;
            unpack2(accA[p], a0, a1);
            unpack2(accB[p], b0, b1);
            unpack2(accC[p], c0x, c1x);
            unpack2(accD[p], d0, d1);
            int ra = rowv[2 * p], rb = rowv[2 * p + 1];
            float e0 = bv[2 * p], e1 = bv[2 * p + 1];
            GdA[ra * NB + b] = a0 + e0;  GdA[rb * NB + b] = a1 + e1;
            GdB[ra * NB + b] = b0 + e0;  GdB[rb * NB + b] = b1 + e1;
            GdC[ra * NB + b] = c0x + e0; GdC[rb * NB + b] = c1x + e1;
            GdD[ra * NB + b] = d0 + e0;  GdD[rb * NB + b] = d1 + e1;
        }
    }
}

// ---------------- persistent LSTM recurrence: 640 threads, 8-way k-split (R12 exact) ----------------
__global__ void __launch_bounds__(R_THREADS, 1) k_recur(
    const float* __restrict__ Whf, const float* __restrict__ Whb)
{
    int bid = blockIdx.x;
    int d = bid >> 6;
    int g = (bid >> 3) & 7;
    int m = bid & 7;
    const float* W = d ? Whb : Whf;

    float* ws = sm;                    // ws[k*152 + r], row pairs packed as ull
    float* hs = sm + HID * 152;        // hs[k*8 + bo]
    ull*  red = (ull*)(hs + HID * RBS);   // 8 * 608 ull

    int t = threadIdx.x;
    int u0 = m * RUPC;
    int cu = HID - u0; if (cu > RUPC) cu = RUPC;

    for (int idx = t; idx < HID * 152; idx += R_THREADS) {
        int k = idx / 152, r = idx - k * 152;
        int ul = r >> 2, gate = r & 3;
        ws[idx] = (ul < cu) ? W[(gate * HID + u0 + ul) * HID + k] : 0.f;
    }
    __syncthreads();

    int ks = t / R_P;                  // 0..7 active, 8 = spare warp
    int p  = t - ks * R_P;             // rowpair 0..75
    bool gemv = (t < R_ACT);
    int k0   = (ks < 4) ? 38 * ks : 152 + 37 * (ks - 4);
    int klen = (ks < 4) ? 38 : 37;
    if (!gemv) { k0 = 0; klen = 0; }
    int bp = (t < 304) ? ks : 0;
    int ul = p >> 1;
    bool doer = (t < 304) && ((p & 1) == 0) && (ul < cu);
    int boff = g * RBS + bp * 2;
    float c0 = 0.f, c1 = 0.f;
    int* cnt = &g_cnt2[d * 8 + g][0];
    const ull* wsu = (const ull*)ws;
    const ulonglong2* hsu = (const ulonglong2*)hs;

    for (int step = 0; step < SEQ; step++) {
        int pos = d ? (SEQ - 1 - step) : step;
        const float* Gp = g_G[d][pos];

        float2 Gv0, Gv1, Gv2, Gv3;
        if (doer) {
            int gb = (u0 + ul) * NB + boff;
            Gv0 = *(const float2*)(Gp + 0 * HID * NB + gb);
            Gv1 = *(const float2*)(Gp + 1 * HID * NB + gb);
            Gv2 = *(const float2*)(Gp + 2 * HID * NB + gb);
            Gv3 = *(const float2*)(Gp + 3 * HID * NB + gb);
        }

        float s0lo = 0.f, s0hi = 0.f, s1lo = 0.f, s1hi = 0.f;

        if (step > 0) {
            if (t == 0) {
                int target = RUS * step;
                int v;
                do {
                    asm volatile("ld.acquire.gpu.global.b32 %0, [%1];" : "=r"(v) : "l"(cnt) : "memory");
                    if (v < target) __nanosleep(20);
                } while (v < target);
            }
            __syncthreads();

            {
                int prev = d ? (SEQ - step) : (step - 1);
                const float4* src = (const float4*)(g_hall[d][prev] + g * (HID * RBS));
                float4* dst = (float4*)hs;
                if (t < HID * RBS / 4) dst[t] = src[t];
            }
            __syncthreads();

            ull a00 = 0, a01 = 0, a02 = 0, a03 = 0;
            ull a10 = 0, a11 = 0, a12 = 0, a13 = 0;
#pragma unroll 2
            for (int kk = 0; kk < klen; kk++) {
                int k = k0 + kk;
                ull w = wsu[k * R_P + p];
                float w0, w1; unpack2(w, w0, w1);
                ull w00 = pack2(w0, w0), w11 = pack2(w1, w1);
                ulonglong2 hA = hsu[k * 2];
                ulonglong2 hB = hsu[k * 2 + 1];
                a00 = fma2(w00, hA.x, a00); a01 = fma2(w00, hA.y, a01);
                a02 = fma2(w00, hB.x, a02); a03 = fma2(w00, hB.y, a03);
                a10 = fma2(w11, hA.x, a10); a11 = fma2(w11, hA.y, a11);
                a12 = fma2(w11, hB.x, a12); a13 = fma2(w11, hB.y, a13);
            }
            if (gemv) {
                red[0 * R_ACT + t] = a00; red[1 * R_ACT + t] = a01;
                red[2 * R_ACT + t] = a02; red[3 * R_ACT + t] = a03;
                red[4 * R_ACT + t] = a10; red[5 * R_ACT + t] = a11;
                red[6 * R_ACT + t] = a12; red[7 * R_ACT + t] = a13;
            }
            __syncthreads();

            if (t < 304) {
                const ull* r0 = red + bp * R_ACT + p;
                const ull* r1 = red + (4 + bp) * R_ACT + p;
                ull s0 = r0[0];
                ull s1 = r1[0];
#pragma unroll
                for (int q = 1; q < R_KS; q++) {
                    s0 = add2(s0, r0[q * R_P]);
                    s1 = add2(s1, r1[q * R_P]);
                }
                unpack2(s0, s0lo, s0hi);
                unpack2(s1, s1lo, s1hi);
            }
        }

        float g2lo = __shfl_down_sync(0xffffffffu, s0lo, 1);
        float g2hi = __shfl_down_sync(0xffffffffu, s0hi, 1);
        float g3lo = __shfl_down_sync(0xffffffffu, s1lo, 1);
        float g3hi = __shfl_down_sync(0xffffffffu, s1hi, 1);

        if (doer) {
            float i0 = fsigm(s0lo + Gv0.x), i1 = fsigm(s0hi + Gv0.y);
            float f0 = fsigm(s1lo + Gv1.x), f1 = fsigm(s1hi + Gv1.y);
            float q0 = ftanh(g2lo + Gv2.x), q1 = ftanh(g2hi + Gv2.y);
            float o0 = fsigm(g3lo + Gv3.x), o1 = fsigm(g3hi + Gv3.y);
            c0 = f0 * c0 + i0 * q0;
            c1 = f1 * c1 + i1 * q1;
            float2 hv;
            hv.x = o0 * ftanh(c0);
            hv.y = o1 * ftanh(c1);
            *(float2*)(g_hall[d][pos] + g * (HID * RBS) + (u0 + ul) * RBS + bp * 2) = hv;
        }

        __syncthreads();
        if (t == 0)
            asm volatile("red.release.gpu.global.add.s32 [%0], 1;" :: "l"(cnt) : "memory");
    }
}

// ---------------- emissions (R12 form: one s per CTA) ----------------
__global__ void k_emit(const float* __restrict__ Wl, const float* __restrict__ bl) {
    int s = blockIdx.x, t = threadIdx.x;  // 256
    __shared__ float wl[600 * NTAG];
    __shared__ float red2[4 * NTAG * NB];
    for (int idx = t; idx < 600 * NTAG; idx += 256) {
        int k = idx / NTAG, j = idx - k * NTAG;
        wl[idx] = Wl[j * 600 + k];
    }
    __syncthreads();
    int b = t & 63, ksx = t >> 6;
    int gof = (b >> 3) * (HID * RBS) + (b & 7);
    float acc[NTAG];
#pragma unroll
    for (int j = 0; j < NTAG; j++) acc[j] = 0.f;
    const float* hf = g_hall[0][s];
    const float* hb = g_hall[1][s];
    int k0 = ksx * 150;
    for (int k = k0; k < k0 + 150; k++) {
        float v = (k < HID) ? hf[gof + k * RBS] : hb[gof + (k - HID) * RBS];
        const float4* w4 = (const float4*)(wl + k * NTAG);
#pragma unroll
        for (int q = 0; q < 3; q++) {
            float4 w = w4[q];
            acc[4 * q + 0] += w.x * v; acc[4 * q + 1] += w.y * v;
            acc[4 * q + 2] += w.z * v; acc[4 * q + 3] += w.w * v;
        }
    }
#pragma unroll
    for (int j = 0; j < NTAG; j++) red2[(ksx * NTAG + j) * NB + b] = acc[j];
    __syncthreads();
    for (int idx = t; idx < NTAG * NB; idx += 256) {
        int j = idx >> 6, b2 = idx & 63;
        float v = red2[(0 * NTAG + j) * NB + b2] + red2[(1 * NTAG + j) * NB + b2]
                + red2[(2 * NTAG + j) * NB + b2] + red2[(3 * NTAG + j) * NB + b2];
        g_emit[s][b2][j] = v + bl[j];
    }
}

// ---------------- CRF forward + gold score + loss ----------------
__global__ void k_crf(const int* __restrict__ tags, const float* __restrict__ trans,
                      float* __restrict__ out) {
    int b = blockIdx.x;
    int j = threadIdx.x;
    float Tcol[NTAG];
#pragma unroll
    for (int i = 0; i < NTAG; i++) Tcol[i] = (j < NTAG) ? trans[i * NTAG + j] : 0.f;
    float dcur = (j < NTAG) ? g_emit[0][b][j] : -1e30f;

    float ts = 0.f;
    for (int s = j; s < SEQ; s += 32) {
        int tg = tags[b * SEQ + s];
        ts += g_emit[s][b][tg];
        if (s < SEQ - 1) ts += trans[tg * NTAG + tags[b * SEQ + s + 1]];
    }
#pragma unroll
    for (int off = 16; off; off >>= 1) ts += __shfl_xor_sync(0xffffffffu, ts, off);

    for (int s = 1; s < SEQ; s++) {
        float v[NTAG];
#pragma unroll
        for (int i = 0; i < NTAG; i++)
            v[i] = __shfl_sync(0xffffffffu, dcur, i) + Tcol[i];
        float mx = v[0];
#pragma unroll
        for (int i = 1; i < NTAG; i++) mx = fmaxf(mx, v[i]);
        float sum = 0.f;
#pragma unroll
        for (int i = 0; i < NTAG; i++) sum += expf(v[i] - mx);
        float e = (j < NTAG) ? g_emit[s][b][j] : 0.f;
        dcur = e + mx + logf(sum);
    }

    float dd = (j < NTAG) ? dcur : -1e30f;
    float mm = dd;
#pragma unroll
    for (int off = 16; off; off >>= 1) mm = fmaxf(mm, __shfl_xor_sync(0xffffffffu, mm, off));
    float se = (j < NTAG) ? expf(dd - mm) : 0.f;
#pragma unroll
    for (int off = 16; off; off >>= 1) se += __shfl_xor_sync(0xffffffffu, se, off);
    if (j == 0) out[b] = mm + logf(se) - ts;
}

// ---------------- launch ----------------
extern "C" void kernel_launch(void* const* d_in, const int* in_sizes, int n_in,
                              void* d_out, int out_size) {
    const int*   sentences = (const int*)d_in[0];
    const int*   tags      = (const int*)d_in[1];
    const float* emb       = (const float*)d_in[2];
    const float* W_ih_f    = (const float*)d_in[3];
    const float* W_hh_f    = (const float*)d_in[4];
    const float* b_f       = (const float*)d_in[5];
    const float* W_ih_b    = (const float*)d_in[6];
    const float* W_hh_b    = (const float*)d_in[7];
    const float* b_b       = (const float*)d_in[8];
    const float* W_lin     = (const float*)d_in[9];
    const float* b_lin     = (const float*)d_in[10];
    const float* trans     = (const float*)d_in[11];
    float* out = (float*)d_out;

    int smem_ip = (HID * IP_ROWS + 8 * IP_CHF) * 4;                   // 102720 B
    int smem_rc = (HID * 152 + HID * RBS) * 4 + R_KS * R_ACT * 8;     // 230912 B
    cudaFuncSetAttribute(k_inproj, cudaFuncAttributeMaxDynamicSharedMemorySize, smem_ip);
    cudaFuncSetAttribute(k_recur,  cudaFuncAttributeMaxDynamicSharedMemorySize, smem_rc);

    k_gather<<<SEQ, 256>>>(sentences, emb);
    dim3 gip(IP_JS, IP_MB, 2);
    k_inproj<<<gip, IP_THREADS, smem_ip>>>(W_ih_f, b_f, W_ih_b, b_b);
    k_recur<<<2 * RBG * RUS, R_THREADS, smem_rc>>>(W_hh_f, W_hh_b);
    k_emit<<<SEQ, 256>>>(W_lin, b_lin);
    k_crf<<<NB, 32>>>(tags, trans, out);
}

// round 17
// speedup vs baseline: 1.2148x; 1.0205x over previous
#include <cuda_runtime.h>
#include <cstdint>
#include <math.h>

#define SEQ 256
#define NB 64
#define HID 300
#define G4 1200
#define NTAG 12

// recurrence: 2 dirs x 8 batch-groups x 8 unit-slices = 128 CTAs  (R12 config — best)
#define RBG 8
#define RUS 8
#define RBS 8
#define RUPC 38
#define R_P 76
#define R_KS 8
#define R_ACT 608
#define R_THREADS 640

// input projection: persistent weights; 7 seq-splits x 20 m x 2 dirs = 280 CTAs (one wave)
// s-blocked (3 s per pass), 3-stage cp.async pipeline with ONE sync per chunk
#define IP_MB 20
#define IP_ROWS 60
#define IP_THREADS 320
#define IP_JS 7
#define IP_SC 37
#define IP_KC 15
#define IP_NKC 20
#define IP_CHF (IP_KC * NB)       // 960 floats per chunk per stream
#define IP_CH4 (IP_CHF / 4)       // 240 float4 per chunk per stream
#define IP_TOT4 (3 * IP_CH4)      // 720 float4 per chunk (all 3 streams)

typedef unsigned long long ull;

__device__ __forceinline__ ull pack2(float lo, float hi) {
    ull r; asm("mov.b64 %0, {%1, %2};" : "=l"(r) : "f"(lo), "f"(hi)); return r;
}
__device__ __forceinline__ void unpack2(ull v, float& lo, float& hi) {
    asm("mov.b64 {%0, %1}, %2;" : "=f"(lo), "=f"(hi) : "l"(v));
}
__device__ __forceinline__ ull fma2(ull a, ull b, ull c) {
    ull d; asm("fma.rn.f32x2 %0, %1, %2, %3;" : "=l"(d) : "l"(a), "l"(b), "l"(c)); return d;
}
__device__ __forceinline__ ull add2(ull a, ull b) {
    ull d; asm("add.rn.f32x2 %0, %1, %2;" : "=l"(d) : "l"(a), "l"(b)); return d;
}
__device__ __forceinline__ float ftanh(float x) {
    float y; asm("tanh.approx.f32 %0, %1;" : "=f"(y) : "f"(x)); return y;
}
__device__ __forceinline__ float fsigm(float x) {
    return 0.5f * ftanh(0.5f * x) + 0.5f;
}
__device__ __forceinline__ uint32_t smem_u32_of(const void* p) {
    uint32_t a;
    asm("{ .reg .u64 t0; cvta.to.shared.u64 t0, %1; cvt.u32.u64 %0, t0; }" : "=r"(a) : "l"(p));
    return a;
}
__device__ __forceinline__ void cpasync16(uint32_t saddr, const void* g) {
    asm volatile("cp.async.cg.shared.global [%0], [%1], 16;" :: "r"(saddr), "l"(g));
}

// ---------------- scratch (device globals; no allocations) ----------------
__device__ float g_XT[SEQ * HID * NB];
__device__ float g_G[2][SEQ][G4 * NB];
__device__ float g_hall[2][SEQ][RBG * HID * RBS];
__device__ float g_emit[SEQ][NB][NTAG];
__device__ int   g_cnt2[16][32];            // per (dir,group) counters, 128B padded

extern __shared__ float sm[];

// ---------------- embedding gather + transpose (+ counter reset) ----------------
__global__ void k_gather(const int* __restrict__ sent, const float* __restrict__ emb) {
    int s = blockIdx.x;
    __shared__ float sx[64][33];
    __shared__ int rows[64];
    int t = threadIdx.x;  // 256
    if (s == 0 && t < 16) g_cnt2[t][0] = 0;
    if (t < 64) rows[t] = sent[t * SEQ + s];
    __syncthreads();
    for (int kc = 0; kc < 10; kc++) {
        int kbase = kc * 32;
        int width = HID - kbase; if (width > 32) width = 32;
        int kk = t & 31, bg = t >> 5;
        if (kk < width) {
            for (int b = bg; b < 64; b += 8)
                sx[b][kk] = emb[rows[b] * HID + kbase + kk];
        }
        __syncthreads();
        int b = t & 63, kg = t >> 6;
        for (int k2 = kg; k2 < width; k2 += 4)
            g_XT[(s * HID + kbase + k2) * NB + b] = sx[b][k2];
        __syncthreads();
    }
}

// ---------------- input projection: persistent weights, 3-stage pipeline, 3 s per pass ----------------
// CTA = (j, m, d): 60 gate rows; triples of s share each weight LDS.
// 3 buffers x 3 streams x 960 floats; ONE __syncthreads per chunk:
//   sync at chunk kc guarantees every warp finished reading chunk kc-1, so the
//   prefetch for kc+2 (same buffer as kc-1) issued right after the sync is safe.
__global__ void __launch_bounds__(IP_THREADS, 2) k_inproj(
    const float* __restrict__ Wf, const float* __restrict__ bf,
    const float* __restrict__ Wb, const float* __restrict__ bb)
{
    int j = blockIdx.x, m = blockIdx.y, d = blockIdx.z;
    const float* W    = d ? Wb : Wf;
    const float* bias = d ? bb : bf;
    float* ws = sm;                        // 18000 floats: ws[k*60 + r]
    float* xb = sm + HID * IP_ROWS;        // 3 bufs x 3 streams x 960 floats
    int t = threadIdx.x;
    int u0 = m * 15;

    int s0 = j * IP_SC;
    int ns = SEQ - s0; if (ns > IP_SC) ns = IP_SC;
    int ntrip = (ns + 2) / 3;
    int slast = s0 + ns - 1;

    uint32_t xb_u32 = smem_u32_of(xb);

    // stage weights once: ws[k*60 + r], r = ul*4 + gate, row = gate*300 + u0 + ul
    for (int idx = t; idx < HID * IP_ROWS; idx += IP_THREADS) {
        int k = idx / IP_ROWS, r = idx - k * IP_ROWS;
        int ul = r >> 2, gate = r & 3;
        ws[idx] = W[(gate * HID + u0 + ul) * HID + k];
    }

    int b = t & 63, rg = t >> 6;   // rg 0..4, owns rows rg*12 .. rg*12+11

    float bv[12];
    int rowv[12];
#pragma unroll
    for (int q = 0; q < 12; q++) {
        int r = rg * 12 + q;
        int row = (r & 3) * HID + u0 + (r >> 2);
        rowv[q] = row;
        bv[q] = bias[row];
    }
    __syncthreads();   // ws ready

    for (int tr = 0; tr < ntrip; tr++) {
        int sA = s0 + 3 * tr;
        int sB = sA + 1; if (sB > slast) sB = slast;
        int sC = sA + 2; if (sC > slast) sC = slast;
        const float4* gS[3];
        gS[0] = (const float4*)(g_XT + (long long)sA * (HID * NB));
        gS[1] = (const float4*)(g_XT + (long long)sB * (HID * NB));
        gS[2] = (const float4*)(g_XT + (long long)sC * (HID * NB));

        // prologue: prefetch chunks 0 (buf0) and 1 (buf1), one commit group each
#pragma unroll
        for (int c0 = 0; c0 < 2; c0++) {
            int kb4 = c0 * IP_CH4;
            uint32_t bufb = xb_u32 + c0 * (3 * IP_CHF * 4);
#pragma unroll
            for (int q = 0; q < 3; q++) {
                int gi = t + q * IP_THREADS;
                if (gi < IP_TOT4) {
                    int st = gi / IP_CH4;
                    int ix = gi - st * IP_CH4;
                    cpasync16(bufb + (st * IP_CHF + ix * 4) * 4, gS[st] + kb4 + ix);
                }
            }
            asm volatile("cp.async.commit_group;");
        }

        ull accA[6], accB[6], accC[6];
#pragma unroll
        for (int p = 0; p < 6; p++) { accA[p] = 0ull; accB[p] = 0ull; accC[p] = 0ull; }

        const ulonglong2* wp = ((const ulonglong2*)ws) + rg * 3;
        int cur = 0;   // kc % 3

        for (int kc = 0; kc < IP_NKC; kc++) {
            // wait for chunk kc's group (one group may remain outstanding)
            if (kc < IP_NKC - 1) asm volatile("cp.async.wait_group 1;");
            else                 asm volatile("cp.async.wait_group 0;");
            __syncthreads();   // chunk kc visible; all warps done reading kc-1

            // prefetch chunk kc+2 into buffer (kc+2)%3 == (kc-1)%3 (now safe)
            if (kc + 2 < IP_NKC) {
                int kb4 = (kc + 2) * IP_CH4;
                int nb = cur + 2; if (nb >= 3) nb -= 3;
                uint32_t bufb = xb_u32 + nb * (3 * IP_CHF * 4);
#pragma unroll
                for (int q = 0; q < 3; q++) {
                    int gi = t + q * IP_THREADS;
                    if (gi < IP_TOT4) {
                        int st = gi / IP_CH4;
                        int ix = gi - st * IP_CH4;
                        cpasync16(bufb + (st * IP_CHF + ix * 4) * 4, gS[st] + kb4 + ix);
                    }
                }
                asm volatile("cp.async.commit_group;");
            }

            const float* base = xb + cur * (3 * IP_CHF);
            const float* xpA = base + b;
            const float* xpB = base + IP_CHF + b;
            const float* xpC = base + 2 * IP_CHF + b;
#pragma unroll 5
            for (int k = 0; k < IP_KC; k++) {
                float xa = xpA[k * NB];
                float xv = xpB[k * NB];
                float xc = xpC[k * NB];
                ull h2a = pack2(xa, xa);
                ull h2b = pack2(xv, xv);
                ull h2c = pack2(xc, xc);
                ulonglong2 w0 = wp[0], w1 = wp[1], w2 = wp[2];
                accA[0] = fma2(w0.x, h2a, accA[0]); accB[0] = fma2(w0.x, h2b, accB[0]); accC[0] = fma2(w0.x, h2c, accC[0]);
                accA[1] = fma2(w0.y, h2a, accA[1]); accB[1] = fma2(w0.y, h2b, accB[1]); accC[1] = fma2(w0.y, h2c, accC[1]);
                accA[2] = fma2(w1.x, h2a, accA[2]); accB[2] = fma2(w1.x, h2b, accB[2]); accC[2] = fma2(w1.x, h2c, accC[2]);
                accA[3] = fma2(w1.y, h2a, accA[3]); accB[3] = fma2(w1.y, h2b, accB[3]); accC[3] = fma2(w1.y, h2c, accC[3]);
                accA[4] = fma2(w2.x, h2a, accA[4]); accB[4] = fma2(w2.x, h2b, accB[4]); accC[4] = fma2(w2.x, h2c, accC[4]);
                accA[5] = fma2(w2.y, h2a, accA[5]); accB[5] = fma2(w2.y, h2b, accB[5]); accC[5] = fma2(w2.y, h2c, accC[5]);
                wp += 15;  // 60 floats per k
            }
            if (++cur >= 3) cur = 0;
        }

        float* GdA = g_G[d][sA];
        float* GdB = g_G[d][sB];
        float* GdC = g_G[d][sC];
#pragma unroll
        for (int p = 0; p < 6; p++) {
            float a0, a1, b0, b1, c0x, c1x;
            unpack2(accA[p], a0, a1);
            unpack2(accB[p], b0, b1);
            unpack2(accC[p], c0x, c1x);
            int ra = rowv[2 * p], rb = rowv[2 * p + 1];
            GdA[ra * NB + b] = a0 + bv[2 * p];
            GdA[rb * NB + b] = a1 + bv[2 * p + 1];
            GdB[ra * NB + b] = b0 + bv[2 * p];
            GdB[rb * NB + b] = b1 + bv[2 * p + 1];
            GdC[ra * NB + b] = c0x + bv[2 * p];
            GdC[rb * NB + b] = c1x + bv[2 * p + 1];
        }
        __syncthreads();   // all reads done before next triple's prologue overwrites buffers
    }
}

// ---------------- persistent LSTM recurrence: 640 threads, 8-way k-split (R12 exact) ----------------
__global__ void __launch_bounds__(R_THREADS, 1) k_recur(
    const float* __restrict__ Whf, const float* __restrict__ Whb)
{
    int bid = blockIdx.x;
    int d = bid >> 6;
    int g = (bid >> 3) & 7;
    int m = bid & 7;
    const float* W = d ? Whb : Whf;

    float* ws = sm;                    // ws[k*152 + r], row pairs packed as ull
    float* hs = sm + HID * 152;        // hs[k*8 + bo]
    ull*  red = (ull*)(hs + HID * RBS);   // 8 * 608 ull

    int t = threadIdx.x;
    int u0 = m * RUPC;
    int cu = HID - u0; if (cu > RUPC) cu = RUPC;

    for (int idx = t; idx < HID * 152; idx += R_THREADS) {
        int k = idx / 152, r = idx - k * 152;
        int ul = r >> 2, gate = r & 3;
        ws[idx] = (ul < cu) ? W[(gate * HID + u0 + ul) * HID + k] : 0.f;
    }
    __syncthreads();

    int ks = t / R_P;                  // 0..7 active, 8 = spare warp
    int p  = t - ks * R_P;             // rowpair 0..75
    bool gemv = (t < R_ACT);
    int k0   = (ks < 4) ? 38 * ks : 152 + 37 * (ks - 4);
    int klen = (ks < 4) ? 38 : 37;
    if (!gemv) { k0 = 0; klen = 0; }
    int bp = (t < 304) ? ks : 0;
    int ul = p >> 1;
    bool doer = (t < 304) && ((p & 1) == 0) && (ul < cu);
    int boff = g * RBS + bp * 2;
    float c0 = 0.f, c1 = 0.f;
    int* cnt = &g_cnt2[d * 8 + g][0];
    const ull* wsu = (const ull*)ws;
    const ulonglong2* hsu = (const ulonglong2*)hs;

    for (int step = 0; step < SEQ; step++) {
        int pos = d ? (SEQ - 1 - step) : step;
        const float* Gp = g_G[d][pos];

        float2 Gv0, Gv1, Gv2, Gv3;
        if (doer) {
            int gb = (u0 + ul) * NB + boff;
            Gv0 = *(const float2*)(Gp + 0 * HID * NB + gb);
            Gv1 = *(const float2*)(Gp + 1 * HID * NB + gb);
            Gv2 = *(const float2*)(Gp + 2 * HID * NB + gb);
            Gv3 = *(const float2*)(Gp + 3 * HID * NB + gb);
        }

        float s0lo = 0.f, s0hi = 0.f, s1lo = 0.f, s1hi = 0.f;

        if (step > 0) {
            if (t == 0) {
                int target = RUS * step;
                int v;
                do {
                    asm volatile("ld.acquire.gpu.global.b32 %0, [%1];" : "=r"(v) : "l"(cnt) : "memory");
                    if (v < target) __nanosleep(20);
                } while (v < target);
            }
            __syncthreads();

            {
                int prev = d ? (SEQ - step) : (step - 1);
                const float4* src = (const float4*)(g_hall[d][prev] + g * (HID * RBS));
                float4* dst = (float4*)hs;
                if (t < HID * RBS / 4) dst[t] = src[t];
            }
            __syncthreads();

            ull a00 = 0, a01 = 0, a02 = 0, a03 = 0;
            ull a10 = 0, a11 = 0, a12 = 0, a13 = 0;
#pragma unroll 2
            for (int kk = 0; kk < klen; kk++) {
                int k = k0 + kk;
                ull w = wsu[k * R_P + p];
                float w0, w1; unpack2(w, w0, w1);
                ull w00 = pack2(w0, w0), w11 = pack2(w1, w1);
                ulonglong2 hA = hsu[k * 2];
                ulonglong2 hB = hsu[k * 2 + 1];
                a00 = fma2(w00, hA.x, a00); a01 = fma2(w00, hA.y, a01);
                a02 = fma2(w00, hB.x, a02); a03 = fma2(w00, hB.y, a03);
                a10 = fma2(w11, hA.x, a10); a11 = fma2(w11, hA.y, a11);
                a12 = fma2(w11, hB.x, a12); a13 = fma2(w11, hB.y, a13);
            }
            if (gemv) {
                red[0 * R_ACT + t] = a00; red[1 * R_ACT + t] = a01;
                red[2 * R_ACT + t] = a02; red[3 * R_ACT + t] = a03;
                red[4 * R_ACT + t] = a10; red[5 * R_ACT + t] = a11;
                red[6 * R_ACT + t] = a12; red[7 * R_ACT + t] = a13;
            }
            __syncthreads();

            if (t < 304) {
                const ull* r0 = red + bp * R_ACT + p;
                const ull* r1 = red + (4 + bp) * R_ACT + p;
                ull s0 = r0[0];
                ull s1 = r1[0];
#pragma unroll
                for (int q = 1; q < R_KS; q++) {
                    s0 = add2(s0, r0[q * R_P]);
                    s1 = add2(s1, r1[q * R_P]);
                }
                unpack2(s0, s0lo, s0hi);
                unpack2(s1, s1lo, s1hi);
            }
        }

        float g2lo = __shfl_down_sync(0xffffffffu, s0lo, 1);
        float g2hi = __shfl_down_sync(0xffffffffu, s0hi, 1);
        float g3lo = __shfl_down_sync(0xffffffffu, s1lo, 1);
        float g3hi = __shfl_down_sync(0xffffffffu, s1hi, 1);

        if (doer) {
            float i0 = fsigm(s0lo + Gv0.x), i1 = fsigm(s0hi + Gv0.y);
            float f0 = fsigm(s1lo + Gv1.x), f1 = fsigm(s1hi + Gv1.y);
            float q0 = ftanh(g2lo + Gv2.x), q1 = ftanh(g2hi + Gv2.y);
            float o0 = fsigm(g3lo + Gv3.x), o1 = fsigm(g3hi + Gv3.y);
            c0 = f0 * c0 + i0 * q0;
            c1 = f1 * c1 + i1 * q1;
            float2 hv;
            hv.x = o0 * ftanh(c0);
            hv.y = o1 * ftanh(c1);
            *(float2*)(g_hall[d][pos] + g * (HID * RBS) + (u0 + ul) * RBS + bp * 2) = hv;
        }

        __syncthreads();
        if (t == 0)
            asm volatile("red.release.gpu.global.add.s32 [%0], 1;" :: "l"(cnt) : "memory");
    }
}

// ---------------- emissions (R12 form: one s per CTA) ----------------
__global__ void k_emit(const float* __restrict__ Wl, const float* __restrict__ bl) {
    int s = blockIdx.x, t = threadIdx.x;  // 256
    __shared__ float wl[600 * NTAG];
    __shared__ float red2[4 * NTAG * NB];
    for (int idx = t; idx < 600 * NTAG; idx += 256) {
        int k = idx / NTAG, j = idx - k * NTAG;
        wl[idx] = Wl[j * 600 + k];
    }
    __syncthreads();
    int b = t & 63, ksx = t >> 6;
    int gof = (b >> 3) * (HID * RBS) + (b & 7);
    float acc[NTAG];
#pragma unroll
    for (int j = 0; j < NTAG; j++) acc[j] = 0.f;
    const float* hf = g_hall[0][s];
    const float* hb = g_hall[1][s];
    int k0 = ksx * 150;
    for (int k = k0; k < k0 + 150; k++) {
        float v = (k < HID) ? hf[gof + k * RBS] : hb[gof + (k - HID) * RBS];
        const float4* w4 = (const float4*)(wl + k * NTAG);
#pragma unroll
        for (int q = 0; q < 3; q++) {
            float4 w = w4[q];
            acc[4 * q + 0] += w.x * v; acc[4 * q + 1] += w.y * v;
            acc[4 * q + 2] += w.z * v; acc[4 * q + 3] += w.w * v;
        }
    }
#pragma unroll
    for (int j = 0; j < NTAG; j++) red2[(ksx * NTAG + j) * NB + b] = acc[j];
    __syncthreads();
    for (int idx = t; idx < NTAG * NB; idx += 256) {
        int j = idx >> 6, b2 = idx & 63;
        float v = red2[(0 * NTAG + j) * NB + b2] + red2[(1 * NTAG + j) * NB + b2]
                + red2[(2 * NTAG + j) * NB + b2] + red2[(3 * NTAG + j) * NB + b2];
        g_emit[s][b2][j] = v + bl[j];
    }
}

// ---------------- CRF forward + gold score + loss (fast exp/log) ----------------
__global__ void k_crf(const int* __restrict__ tags, const float* __restrict__ trans,
                      float* __restrict__ out) {
    int b = blockIdx.x;
    int j = threadIdx.x;
    float Tcol[NTAG];
#pragma unroll
    for (int i = 0; i < NTAG; i++) Tcol[i] = (j < NTAG) ? trans[i * NTAG + j] : 0.f;
    float dcur = (j < NTAG) ? g_emit[0][b][j] : -1e30f;

    float ts = 0.f;
    for (int s = j; s < SEQ; s += 32) {
        int tg = tags[b * SEQ + s];
        ts += g_emit[s][b][tg];
        if (s < SEQ - 1) ts += trans[tg * NTAG + tags[b * SEQ + s + 1]];
    }
#pragma unroll
    for (int off = 16; off; off >>= 1) ts += __shfl_xor_sync(0xffffffffu, ts, off);

    for (int s = 1; s < SEQ; s++) {
        float v[NTAG];
#pragma unroll
        for (int i = 0; i < NTAG; i++)
            v[i] = __shfl_sync(0xffffffffu, dcur, i) + Tcol[i];
        float mx = v[0];
#pragma unroll
        for (int i = 1; i < NTAG; i++) mx = fmaxf(mx, v[i]);
        float sum = 0.f;
#pragma unroll
        for (int i = 0; i < NTAG; i++) sum += __expf(v[i] - mx);
        float e = (j < NTAG) ? g_emit[s][b][j] : 0.f;
        dcur = e + mx + __logf(sum);
    }

    float dd = (j < NTAG) ? dcur : -1e30f;
    float mm = dd;
#pragma unroll
    for (int off = 16; off; off >>= 1) mm = fmaxf(mm, __shfl_xor_sync(0xffffffffu, mm, off));
    float se = (j < NTAG) ? __expf(dd - mm) : 0.f;
#pragma unroll
    for (int off = 16; off; off >>= 1) se += __shfl_xor_sync(0xffffffffu, se, off);
    if (j == 0) out[b] = mm + __logf(se) - ts;
}

// ---------------- launch ----------------
extern "C" void kernel_launch(void* const* d_in, const int* in_sizes, int n_in,
                              void* d_out, int out_size) {
    const int*   sentences = (const int*)d_in[0];
    const int*   tags      = (const int*)d_in[1];
    const float* emb       = (const float*)d_in[2];
    const float* W_ih_f    = (const float*)d_in[3];
    const float* W_hh_f    = (const float*)d_in[4];
    const float* b_f       = (const float*)d_in[5];
    const float* W_ih_b    = (const float*)d_in[6];
    const float* W_hh_b    = (const float*)d_in[7];
    const float* b_b       = (const float*)d_in[8];
    const float* W_lin     = (const float*)d_in[9];
    const float* b_lin     = (const float*)d_in[10];
    const float* trans     = (const float*)d_in[11];
    float* out = (float*)d_out;

    int smem_ip = (HID * IP_ROWS + 9 * IP_CHF) * 4;                   // 106560 B
    int smem_rc = (HID * 152 + HID * RBS) * 4 + R_KS * R_ACT * 8;     // 230912 B
    cudaFuncSetAttribute(k_inproj, cudaFuncAttributeMaxDynamicSharedMemorySize, smem_ip);
    cudaFuncSetAttribute(k_recur,  cudaFuncAttributeMaxDynamicSharedMemorySize, smem_rc);

    k_gather<<<SEQ, 256>>>(sentences, emb);
    dim3 gip(IP_JS, IP_MB, 2);
    k_inproj<<<gip, IP_THREADS, smem_ip>>>(W_ih_f, b_f, W_ih_b, b_b);
    k_recur<<<2 * RBG * RUS, R_THREADS, smem_rc>>>(W_hh_f, W_hh_b);
    k_emit<<<SEQ, 256>>>(W_lin, b_lin);
    k_crf<<<NB, 32>>>(tags, trans, out);
}